// round 2
// baseline (speedup 1.0000x reference)
#include <cuda_runtime.h>

// Problem constants
#define Nn 64
#define Cc 64
#define Tt 300
#define Vv 25
#define Ss 3
#define Ii 16
#define TV 7500           // T*V
#define NS 192            // N*S
#define CNT_BN 480000.0f  // N*T*V per channel
#define EPS_BN 1e-5f

// ---------------- scratch (__device__ globals: allocation-free) ----------------
__device__ float g_a[(size_t)NS * Ii * TV];       // [n][s][i][t*v]
__device__ float g_b[(size_t)NS * Ii * TV];
__device__ float g_scores[NS * Vv * Vv];          // [n][s][v][w]
__device__ float g_adapt[NS * Vv * 28];           // [n][s][v][w padded to 28]
__device__ float g_z[(size_t)NS * Cc * TV];       // [n][k=s*64+c][t*w]
__device__ float g_y[(size_t)Nn * Cc * TV];       // [n][o][t*w]
__device__ float g_wdt[Ss * Cc * Cc];             // [k][o]
__device__ float g_bdsum[Cc];
__device__ float g_stats[2 * Cc];                 // sum, sumsq per channel

// ---------------- K0: prep ----------------------------------------------------
__global__ void k_prep(const float* __restrict__ wd, const float* __restrict__ bd) {
    int idx = blockIdx.x * 256 + threadIdx.x;
    if (idx < NS * Vv * Vv) g_scores[idx] = 0.f;
    if (idx < Ss * Cc * Cc) {
        int k = idx >> 6, o = idx & 63;
        int s = k >> 6, c = k & 63;
        g_wdt[idx] = wd[(s * 64 + o) * 64 + c];
    }
    if (idx < Cc) g_bdsum[idx] = bd[idx] + bd[64 + idx] + bd[128 + idx];
    if (idx < 2 * Cc) g_stats[idx] = 0.f;
}

// ---------------- K1: out = W@X + bias  ([16,64]@[64,7500]) -------------------
// grid (192, 8), block 256. Each thread: 4 cols (float4) x 16 rows.
__global__ void k_proj(const float* __restrict__ x,
                       const float* __restrict__ w, const float* __restrict__ b,
                       float* __restrict__ out) {
    int ns = blockIdx.x;
    int n = ns / Ss, s = ns % Ss;
    __shared__ float wt[Cc * Ii];   // [c][i] transposed
    __shared__ float bs[Ii];
    int tid = threadIdx.x;
    for (int j = tid; j < Cc * Ii; j += 256) {
        int c = j >> 4, i = j & 15;
        wt[j] = w[s * Ii * Cc + i * Cc + c];
    }
    if (tid < Ii) bs[tid] = b[s * Ii + tid];
    __syncthreads();

    int col0 = blockIdx.y * 1024 + tid * 4;
    if (col0 >= TV) return;      // 7500 % 4 == 0: full float4 always valid here
    const float* xp = x + (size_t)n * Cc * TV + col0;

    float4 acc[Ii];
#pragma unroll
    for (int i = 0; i < Ii; i++) acc[i] = make_float4(0.f, 0.f, 0.f, 0.f);

    for (int c = 0; c < Cc; c++) {
        float4 xr = *(const float4*)(xp + (size_t)c * TV);
#pragma unroll
        for (int iq = 0; iq < 4; iq++) {
            float4 wv = *(const float4*)&wt[c * 16 + iq * 4];
            acc[iq * 4 + 0].x += wv.x * xr.x; acc[iq * 4 + 0].y += wv.x * xr.y;
            acc[iq * 4 + 0].z += wv.x * xr.z; acc[iq * 4 + 0].w += wv.x * xr.w;
            acc[iq * 4 + 1].x += wv.y * xr.x; acc[iq * 4 + 1].y += wv.y * xr.y;
            acc[iq * 4 + 1].z += wv.y * xr.z; acc[iq * 4 + 1].w += wv.y * xr.w;
            acc[iq * 4 + 2].x += wv.z * xr.x; acc[iq * 4 + 2].y += wv.z * xr.y;
            acc[iq * 4 + 2].z += wv.z * xr.z; acc[iq * 4 + 2].w += wv.z * xr.w;
            acc[iq * 4 + 3].x += wv.w * xr.x; acc[iq * 4 + 3].y += wv.w * xr.y;
            acc[iq * 4 + 3].z += wv.w * xr.z; acc[iq * 4 + 3].w += wv.w * xr.w;
        }
    }
    float* op = out + (size_t)ns * Ii * TV + col0;
#pragma unroll
    for (int i = 0; i < Ii; i++) {
        float4 o = acc[i];
        float bi = bs[i];
        o.x += bi; o.y += bi; o.z += bi; o.w += bi;
        *(float4*)(op + (size_t)i * TV) = o;
    }
}

// ---------------- K2: scores[v,w] += sum_{i,t} a[i,t,v]*b[i,t,w] ---------------
// grid (192, 2) t-chunks of 150; batches of 10 t per sync round.
__global__ void k_scores() {
    int ns = blockIdx.x;
    int tbase = blockIdx.y * 150;
    __shared__ float at[10 * Ii * 28], bt[10 * Ii * 28], gsm[Vv * Vv];
    int tid = threadIdx.x;
    for (int j = tid; j < Vv * Vv; j += 256) gsm[j] = 0.f;

    int wrp = tid >> 5, lane = tid & 31;
    int ig = tid >> 6, item = tid & 63;
    bool active = item < 49;
    int v0 = (item / 7) * 4, w0 = (item % 7) * 4;

    float greg[16];
#pragma unroll
    for (int r = 0; r < 16; r++) greg[r] = 0.f;

    const float* abase = g_a + (size_t)ns * Ii * TV;
    const float* bbase = g_b + (size_t)ns * Ii * TV;

    for (int rb = 0; rb < 15; rb++) {
        int t0 = tbase + rb * 10;
        __syncthreads();
        // fill: 160 rows (t'*16+i), 28 cols each; warp handles 20 rows
        if (lane < 28) {
            for (int r = 0; r < 20; r++) {
                int row = wrp * 20 + r;
                int tp = row >> 4, i = row & 15;
                float va = 0.f, vb = 0.f;
                if (lane < Vv) {
                    size_t off = (size_t)i * TV + (size_t)(t0 + tp) * Vv + lane;
                    va = abase[off];
                    vb = bbase[off];
                }
                at[row * 28 + lane] = va;
                bt[row * 28 + lane] = vb;
            }
        }
        __syncthreads();
        if (active) {
            for (int tp = 0; tp < 10; tp++) {
#pragma unroll
                for (int ii = 0; ii < 4; ii++) {
                    int row = tp * 16 + ig * 4 + ii;
                    float4 av = *(const float4*)&at[row * 28 + v0];
                    float4 bv = *(const float4*)&bt[row * 28 + w0];
                    greg[0]  += av.x * bv.x; greg[1]  += av.x * bv.y; greg[2]  += av.x * bv.z; greg[3]  += av.x * bv.w;
                    greg[4]  += av.y * bv.x; greg[5]  += av.y * bv.y; greg[6]  += av.y * bv.z; greg[7]  += av.y * bv.w;
                    greg[8]  += av.z * bv.x; greg[9]  += av.z * bv.y; greg[10] += av.z * bv.z; greg[11] += av.z * bv.w;
                    greg[12] += av.w * bv.x; greg[13] += av.w * bv.y; greg[14] += av.w * bv.z; greg[15] += av.w * bv.w;
                }
            }
        }
    }
    __syncthreads();
    if (active) {
#pragma unroll
        for (int r = 0; r < 4; r++)
#pragma unroll
            for (int cix = 0; cix < 4; cix++) {
                int v = v0 + r, w = w0 + cix;
                if (v < Vv && w < Vv) atomicAdd(&gsm[v * Vv + w], greg[r * 4 + cix]);
            }
    }
    __syncthreads();
    for (int j = tid; j < Vv * Vv; j += 256) atomicAdd(&g_scores[ns * Vv * Vv + j], gsm[j]);
}

// ---------------- K3: softmax over v + adapt = A+W+attn (padded to 28) --------
__global__ void k_softmax(const float* __restrict__ A, const float* __restrict__ W) {
    int ns = blockIdx.x;
    int s = ns % Ss;
    int w = threadIdx.x;
    if (w >= 28) return;
    if (w >= Vv) {   // padding columns -> 0
#pragma unroll
        for (int v = 0; v < Vv; v++) g_adapt[ns * Vv * 28 + v * 28 + w] = 0.f;
        return;
    }
    float col[Vv];
    const float inv = 1.f / 4800.f;
    float m = -1e30f;
#pragma unroll
    for (int v = 0; v < Vv; v++) {
        col[v] = g_scores[ns * Vv * Vv + v * Vv + w] * inv;
        m = fmaxf(m, col[v]);
    }
    float sum = 0.f;
#pragma unroll
    for (int v = 0; v < Vv; v++) { col[v] = __expf(col[v] - m); sum += col[v]; }
    float r = 1.f / sum;
#pragma unroll
    for (int v = 0; v < Vv; v++) {
        int off = s * Vv * Vv + v * Vv + w;
        g_adapt[ns * Vv * 28 + v * 28 + w] = A[off] + W[off] + col[v] * r;
    }
}

// ---------------- K4: z[n,s,c,t,w] = sum_v x[n,c,t,v]*adapt[n,s,v,w] ----------
// grid (192, 10); block 256 = 8 warps; warp handles 8 c (2 at a time).
// dyn smem: 704 (adapt padded) + 8*1600 (per-warp staging) floats.
__global__ void k_z(const float* __restrict__ x) {
    extern __shared__ float sm[];
    float* ad = sm;            // [v][28], 700 used, pad 704
    float* buf = sm + 704;     // 8 * 1600
    int ns = blockIdx.x;
    int n = ns / Ss;
    int tid = threadIdx.x;
    for (int j = tid; j < Vv * 28; j += 256) ad[j] = g_adapt[ns * Vv * 28 + j];
    __syncthreads();

    int t0 = blockIdx.y * 32;
    int tt = min(32, Tt - t0);
    int wrp = tid >> 5, lane = tid & 31;
    float* wb = buf + wrp * 1600;

    for (int cp = 0; cp < 4; cp++) {
        int c0 = wrp * 8 + cp * 2;
#pragma unroll
        for (int cc = 0; cc < 2; cc++) {
            const float* xp = x + ((size_t)(n * Cc + c0 + cc) * Tt + t0) * Vv;
            for (int j = lane; j < tt * Vv; j += 32) wb[cc * 800 + j] = xp[j];
        }
        __syncwarp();
        float xv0[Vv], xv1[Vv];
        if (lane < tt) {
#pragma unroll
            for (int v = 0; v < Vv; v++) {
                xv0[v] = wb[lane * Vv + v];
                xv1[v] = wb[800 + lane * Vv + v];
            }
        }
        __syncwarp();
        if (lane < tt) {
#pragma unroll
            for (int q = 0; q < 7; q++) {
                float a0x = 0.f, a0y = 0.f, a0z = 0.f, a0w = 0.f;
                float a1x = 0.f, a1y = 0.f, a1z = 0.f, a1w = 0.f;
#pragma unroll
                for (int v = 0; v < Vv; v++) {
                    float4 a4 = *(const float4*)&ad[v * 28 + q * 4];
                    a0x += xv0[v] * a4.x; a0y += xv0[v] * a4.y;
                    a0z += xv0[v] * a4.z; a0w += xv0[v] * a4.w;
                    a1x += xv1[v] * a4.x; a1y += xv1[v] * a4.y;
                    a1z += xv1[v] * a4.z; a1w += xv1[v] * a4.w;
                }
                int w = q * 4;
                wb[lane * Vv + w] = a0x;           wb[800 + lane * Vv + w] = a1x;
                if (w + 1 < Vv) { wb[lane * Vv + w + 1] = a0y; wb[800 + lane * Vv + w + 1] = a1y; }
                if (w + 2 < Vv) { wb[lane * Vv + w + 2] = a0z; wb[800 + lane * Vv + w + 2] = a1z; }
                if (w + 3 < Vv) { wb[lane * Vv + w + 3] = a0w; wb[800 + lane * Vv + w + 3] = a1w; }
            }
        }
        __syncwarp();
#pragma unroll
        for (int cc = 0; cc < 2; cc++) {
            float* zp = g_z + ((size_t)(ns * Cc + c0 + cc) * Tt + t0) * Vv;
            for (int j = lane; j < tt * Vv; j += 32) zp[j] = wb[cc * 800 + j];
        }
        __syncwarp();
    }
}

// ---------------- K5: y[n] = WDt^T[64,192] @ z[n][192,7500] + bdsum + stats ---
// grid (64, 59), block 256. BM=64, BN=128, BK=16; thread tile 8x4; double-buffered.
__global__ void k_gemm() {
    __shared__ float As[2][16][64];
    __shared__ float Bs[2][16][128];
    int n = blockIdx.x;
    int tw0 = blockIdx.y * 128;
    int tid = threadIdx.x;
    int ty = tid >> 5, tx = tid & 31;

    float acc[8][4];
#pragma unroll
    for (int r = 0; r < 8; r++)
#pragma unroll
        for (int q = 0; q < 4; q++) acc[r][q] = 0.f;

    const float* zb = g_z + (size_t)n * 192 * TV;

    // A regs: 4 floats; B regs: 2 float4
    float ar[4];
    float4 br[2];

    auto ldg_tile = [&](int kt) {
        int k0 = kt * 16;
#pragma unroll
        for (int u = 0; u < 4; u++) {
            int j = tid + u * 256;              // 1024 elems
            ar[u] = g_wdt[k0 * 64 + j];
        }
#pragma unroll
        for (int u = 0; u < 2; u++) {
            int j4 = tid + u * 256;             // 512 float4 = 2048 floats
            int kk = j4 >> 5, c4 = j4 & 31;
            int tw = tw0 + c4 * 4;
            if (tw < TV)
                br[u] = *(const float4*)(zb + (size_t)(k0 + kk) * TV + tw);
            else
                br[u] = make_float4(0.f, 0.f, 0.f, 0.f);
        }
    };
    auto sts_tile = [&](int buf) {
#pragma unroll
        for (int u = 0; u < 4; u++) {
            int j = tid + u * 256;
            As[buf][j >> 6][j & 63] = ar[u];
        }
#pragma unroll
        for (int u = 0; u < 2; u++) {
            int j4 = tid + u * 256;
            int kk = j4 >> 5, c4 = j4 & 31;
            *(float4*)&Bs[buf][kk][c4 * 4] = br[u];
        }
    };

    ldg_tile(0);
    sts_tile(0);
    __syncthreads();

    for (int kt = 0; kt < 12; kt++) {
        int cur = kt & 1;
        if (kt < 11) ldg_tile(kt + 1);
#pragma unroll
        for (int kk = 0; kk < 16; kk++) {
            float4 b4 = *(const float4*)&Bs[cur][kk][tx * 4];
            float4 a0 = *(const float4*)&As[cur][kk][ty * 8];
            float4 a1 = *(const float4*)&As[cur][kk][ty * 8 + 4];
            float av[8] = {a0.x, a0.y, a0.z, a0.w, a1.x, a1.y, a1.z, a1.w};
            float bv[4] = {b4.x, b4.y, b4.z, b4.w};
#pragma unroll
            for (int r = 0; r < 8; r++)
#pragma unroll
                for (int q = 0; q < 4; q++) acc[r][q] += av[r] * bv[q];
        }
        if (kt < 11) {
            sts_tile((kt + 1) & 1);
            __syncthreads();
        }
    }

    // epilogue: bias + store + fused BN partial stats
#pragma unroll
    for (int r = 0; r < 8; r++) {
        int o = ty * 8 + r;
        float bias = g_bdsum[o];
        float* yp = g_y + (size_t)(n * Cc + o) * TV;
        float s1 = 0.f, s2 = 0.f;
#pragma unroll
        for (int q = 0; q < 4; q++) {
            int tw = tw0 + tx * 4 + q;
            if (tw < TV) {
                float v = acc[r][q] + bias;
                yp[tw] = v;
                s1 += v; s2 += v * v;
            }
        }
        // butterfly reduce across the 32 lanes (they cover all 128 cols of row o)
#pragma unroll
        for (int d = 16; d > 0; d >>= 1) {
            s1 += __shfl_xor_sync(0xffffffffu, s1, d);
            s2 += __shfl_xor_sync(0xffffffffu, s2, d);
        }
        if (tx == 0) {
            atomicAdd(&g_stats[o], s1);
            atomicAdd(&g_stats[64 + o], s2);
        }
    }
}

// ---------------- K7: normalize + gamma/beta + residual + relu ----------------
__global__ void k_final(const float* __restrict__ x,
                        const float* __restrict__ gamma, const float* __restrict__ beta,
                        float* __restrict__ out) {
    int i4 = blockIdx.x * 256 + threadIdx.x;        // 7,680,000 float4s
    int c = (i4 / 1875) & 63;                        // TV/4 = 1875
    float s1 = g_stats[c], s2 = g_stats[64 + c];
    float mean = s1 / CNT_BN;
    float var = s2 / CNT_BN - mean * mean;
    float scale = gamma[c] * rsqrtf(var + EPS_BN);
    float bet = beta[c];
    float4 yv = ((const float4*)g_y)[i4];
    float4 xv = ((const float4*)x)[i4];
    float4 o;
    o.x = fmaxf(0.f, (yv.x - mean) * scale + bet + xv.x);
    o.y = fmaxf(0.f, (yv.y - mean) * scale + bet + xv.y);
    o.z = fmaxf(0.f, (yv.z - mean) * scale + bet + xv.z);
    o.w = fmaxf(0.f, (yv.w - mean) * scale + bet + xv.w);
    ((float4*)out)[i4] = o;
}

// ---------------- launch ------------------------------------------------------
extern "C" void kernel_launch(void* const* d_in, const int* in_sizes, int n_in,
                              void* d_out, int out_size) {
    const float* x     = (const float*)d_in[0];
    const float* A     = (const float*)d_in[1];
    const float* W     = (const float*)d_in[2];
    const float* wa    = (const float*)d_in[3];
    const float* ba    = (const float*)d_in[4];
    const float* wb    = (const float*)d_in[5];
    const float* bb    = (const float*)d_in[6];
    const float* wd    = (const float*)d_in[7];
    const float* bd    = (const float*)d_in[8];
    const float* gamma = (const float*)d_in[9];
    const float* beta  = (const float*)d_in[10];
    float* out = (float*)d_out;

    static bool attr_set = false;
    if (!attr_set) {
        cudaFuncSetAttribute(k_z, cudaFuncAttributeMaxDynamicSharedMemorySize, 56 * 1024);
        attr_set = true;
    }

    float* ga;
    float* gb;
    cudaGetSymbolAddress((void**)&ga, g_a);
    cudaGetSymbolAddress((void**)&gb, g_b);

    k_prep<<<472, 256>>>(wd, bd);
    k_proj<<<dim3(NS, 8), 256>>>(x, wa, ba, ga);
    k_proj<<<dim3(NS, 8), 256>>>(x, wb, bb, gb);
    k_scores<<<dim3(NS, 2), 256>>>();
    k_softmax<<<NS, 32>>>(A, W);
    k_z<<<dim3(NS, 10), 256, (704 + 8 * 1600) * sizeof(float)>>>(x);
    k_gemm<<<dim3(Nn, 59), 256>>>();
    k_final<<<30000, 256>>>(x, gamma, beta, out);
}

// round 3
// speedup vs baseline: 1.0417x; 1.0417x over previous
#include <cuda_runtime.h>

// Problem constants
#define Nn 64
#define Cc 64
#define Tt 300
#define Vv 25
#define Ss 3
#define Ii 16
#define TV 7500           // T*V
#define NS 192            // N*S
#define CNT_BN 480000.0f  // N*T*V per channel
#define EPS_BN 1e-5f

// ---------------- scratch (__device__ globals) --------------------------------
__device__ float g_scores[NS * 625];              // [ns][v][w]
__device__ float g_adapt[NS * 700];               // [ns][v][w padded 28]
__device__ float g_y[(size_t)Nn * Cc * TV];       // [n][o][tw]
__device__ float g_wdt[Ss * Cc * Cc];             // [k=s*64+c][o]
__device__ float g_bdsum[Cc];
__device__ float g_stats[2 * Cc];

// ---------------- K0: prep ----------------------------------------------------
__global__ void k_prep(const float* __restrict__ wd, const float* __restrict__ bd) {
    int idx = blockIdx.x * 256 + threadIdx.x;
    if (idx < NS * 625) g_scores[idx] = 0.f;
    if (idx < Ss * Cc * Cc) {
        int k = idx >> 6, o = idx & 63;
        int s = k >> 6, c = k & 63;
        g_wdt[idx] = wd[(s * 64 + o) * 64 + c];
    }
    if (idx < Cc) g_bdsum[idx] = bd[idx] + bd[64 + idx] + bd[128 + idx];
    if (idx < 2 * Cc) g_stats[idx] = 0.f;
}

// ---------------- K1: fused projection + score accumulation -------------------
// grid (192, 3): (ns, 100-t chunk). block 256. dyn smem 20625 floats.
// Per 20-t batch: proj [32,64]@[64,500] -> ab smem; then score outer products.
__global__ void __launch_bounds__(256, 2)
k_attn(const float* __restrict__ x,
       const float* __restrict__ wa, const float* __restrict__ ba,
       const float* __restrict__ wb, const float* __restrict__ bb) {
    extern __shared__ float sm[];
    float* wab  = sm;                   // [64 c][32 row]
    float* ab   = sm + 2048;            // [32 row][20 t' * 28]
    float* gsm  = sm + 2048 + 17920;    // [625]
    float* bias = gsm + 625;            // [32]

    int ns = blockIdx.x;
    int n = ns / Ss, s = ns - n * Ss;
    int tid = threadIdx.x;

    for (int j = tid; j < 2048; j += 256) {
        int c = j >> 5, row = j & 31;
        wab[c * 32 + row] = (row < 16) ? wa[(s * 16 + row) * 64 + c]
                                       : wb[(s * 16 + row - 16) * 64 + c];
    }
    if (tid < 32) bias[tid] = (tid < 16) ? ba[s * 16 + tid] : bb[s * 16 + tid - 16];
    for (int j = tid; j < 625; j += 256) gsm[j] = 0.f;
    // zero the 3 pad columns (v=25..27) of every (row, t') so score reads are clean
    for (int j = tid; j < 1920; j += 256) {
        int row = j / 60, rem = j - row * 60;
        ab[row * 560 + (rem / 3) * 28 + 25 + rem % 3] = 0.f;
    }
    __syncthreads();

    // proj mapping: 4 row-groups (8 rows) x 63 col-groups (8 cols)
    int rg = tid / 63, cg = tid - rg * 63;
    bool pact = (tid < 252);
    // scores mapping: 4 i-groups x 49 (v0,w0) tiles
    int tq = tid / 49, item = tid - tq * 49;
    bool sact = (tid < 196);
    int v0 = (item / 7) * 4, w0 = (item % 7) * 4;

    float greg[16];
#pragma unroll
    for (int r = 0; r < 16; r++) greg[r] = 0.f;

    const float* xn = x + (size_t)n * Cc * TV;
    int twchunk = blockIdx.y * 2500;    // 100 t * 25 v

    for (int b = 0; b < 5; b++) {
        int twbase = twchunk + b * 500;
        // ---- projection: acc[8 rows][8 cols] ----
        float acc[8][8];
        if (pact) {
#pragma unroll
            for (int r = 0; r < 8; r++)
#pragma unroll
                for (int j = 0; j < 8; j++) acc[r][j] = 0.f;
            int colb = cg * 8;
            const float* xcol = xn + twbase + colb;
            bool m1 = (colb + 4 < 500);
            for (int k = 0; k < 64; k++) {
                float4 a0 = *(const float4*)&wab[k * 32 + rg * 8];
                float4 a1 = *(const float4*)&wab[k * 32 + rg * 8 + 4];
                const float* xr = xcol + (size_t)k * TV;
                float4 b0 = *(const float4*)xr;   // colb<=496 -> cols colb..colb+3 always <500
                float4 b1 = m1 ? *(const float4*)(xr + 4) : make_float4(0.f, 0.f, 0.f, 0.f);
                float av[8] = {a0.x, a0.y, a0.z, a0.w, a1.x, a1.y, a1.z, a1.w};
                float bv[8] = {b0.x, b0.y, b0.z, b0.w, b1.x, b1.y, b1.z, b1.w};
#pragma unroll
                for (int r = 0; r < 8; r++)
#pragma unroll
                    for (int j = 0; j < 8; j++) acc[r][j] += av[r] * bv[j];
            }
            // write to ab with bias, layout [row][t'*28 + v]
#pragma unroll
            for (int j = 0; j < 8; j++) {
                int col = colb + j;
                if (col < 500) {
                    int tp = col / 25, v = col - tp * 25;
#pragma unroll
                    for (int r = 0; r < 8; r++) {
                        int row = rg * 8 + r;
                        ab[row * 560 + tp * 28 + v] = acc[r][j] + bias[row];
                    }
                }
            }
        }
        __syncthreads();
        // ---- score accumulation ----
        if (sact) {
#pragma unroll
            for (int i4 = 0; i4 < 4; i4++) {
                const float* ia = ab + (tq * 4 + i4) * 560;
                const float* ib = ab + (16 + tq * 4 + i4) * 560;
                for (int tp = 0; tp < 20; tp++) {
                    float4 av = *(const float4*)(ia + tp * 28 + v0);
                    float4 bv = *(const float4*)(ib + tp * 28 + w0);
                    greg[0]  += av.x * bv.x; greg[1]  += av.x * bv.y; greg[2]  += av.x * bv.z; greg[3]  += av.x * bv.w;
                    greg[4]  += av.y * bv.x; greg[5]  += av.y * bv.y; greg[6]  += av.y * bv.z; greg[7]  += av.y * bv.w;
                    greg[8]  += av.z * bv.x; greg[9]  += av.z * bv.y; greg[10] += av.z * bv.z; greg[11] += av.z * bv.w;
                    greg[12] += av.w * bv.x; greg[13] += av.w * bv.y; greg[14] += av.w * bv.z; greg[15] += av.w * bv.w;
                }
            }
        }
        __syncthreads();
    }
    if (sact) {
#pragma unroll
        for (int r = 0; r < 4; r++)
#pragma unroll
            for (int cix = 0; cix < 4; cix++) {
                int v = v0 + r, w = w0 + cix;
                if (v < Vv && w < Vv) atomicAdd(&gsm[v * 25 + w], greg[r * 4 + cix]);
            }
    }
    __syncthreads();
    for (int j = tid; j < 625; j += 256) atomicAdd(&g_scores[ns * 625 + j], gsm[j]);
}

// ---------------- K2: softmax over v + adapt = A+W+attn (padded 28) -----------
__global__ void k_softmax(const float* __restrict__ A, const float* __restrict__ W) {
    int ns = blockIdx.x;
    int s = ns % Ss;
    int w = threadIdx.x;
    if (w >= 28) return;
    if (w >= Vv) {
#pragma unroll
        for (int v = 0; v < Vv; v++) g_adapt[ns * 700 + v * 28 + w] = 0.f;
        return;
    }
    float col[Vv];
    const float inv = 1.f / 4800.f;
    float m = -1e30f;
#pragma unroll
    for (int v = 0; v < Vv; v++) {
        col[v] = g_scores[ns * 625 + v * 25 + w] * inv;
        m = fmaxf(m, col[v]);
    }
    float sum = 0.f;
#pragma unroll
    for (int v = 0; v < Vv; v++) { col[v] = __expf(col[v] - m); sum += col[v]; }
    float r = 1.f / sum;
#pragma unroll
    for (int v = 0; v < Vv; v++) {
        int off = s * 625 + v * 25 + w;
        g_adapt[ns * 700 + v * 28 + w] = A[off] + W[off] + col[v] * r;
    }
}

// ---------------- K3: fused z + GEMM + bias + BN-stats ------------------------
// grid (64, 30): (n, 10-t tile -> 250 cols). block 256.
// Per 8-c chunk: stage x, compute z-tile (3 subsets) in smem, GEMM-accumulate.
__global__ void __launch_bounds__(256, 2) k_fused(const float* __restrict__ x) {
    __shared__ float ad3[2100];        // [s][v][28]
    __shared__ float xs[8 * 250];      // [cc][t'*25+v]
    __shared__ float zt[24 * 256];     // [k=s*8+cc][col] (cols 250 used)
    __shared__ float wds[24 * 64];     // [k][o]

    int n = blockIdx.x, tile = blockIdx.y;
    int t0 = tile * 10;
    int tid = threadIdx.x;
    int ty = tid >> 5, tx = tid & 31;

    for (int j = tid; j < 2100; j += 256) ad3[j] = g_adapt[n * 3 * 700 + j];

    float acc[8][8];
#pragma unroll
    for (int r = 0; r < 8; r++)
#pragma unroll
        for (int j = 0; j < 8; j++) acc[r][j] = 0.f;

    int zs = tid / 80;                 // subset (0..2) for z-compute threads
    int zr = tid - zs * 80;
    int zc = zr / 10, ztt = zr - zc * 10;
    bool zact = (tid < 240);

    for (int chunk = 0; chunk < 8; chunk++) {
        int c0 = chunk * 8;
        __syncthreads();   // previous GEMM readers done before overwriting xs/zt
        for (int j = tid; j < 1000; j += 256) {
            int cc = j / 125, j2 = j - cc * 125;
            *(float2*)&xs[cc * 250 + j2 * 2] =
                *(const float2*)(x + (size_t)(n * Cc + c0 + cc) * TV + t0 * 25 + j2 * 2);
        }
        for (int j = tid; j < 1536; j += 256) {
            int row = j >> 6, o = j & 63;
            int s = row >> 3, cc = row & 7;
            wds[row * 64 + o] = g_wdt[((s << 6) + c0 + cc) * 64 + o];
        }
        __syncthreads();
        // z-compute: zt[s*8+cc][t'*25+w] = sum_v xs[cc][t'*25+v] * ad3[s][v][w]
        if (zact) {
            int krow = zs * 8 + zc;
            const float* xrow = xs + zc * 250 + ztt * 25;
            const float* adp = ad3 + zs * 700;
            float* zrow = zt + krow * 256 + ztt * 25;
#pragma unroll
            for (int q = 0; q < 7; q++) {
                float4 oq = make_float4(0.f, 0.f, 0.f, 0.f);
#pragma unroll
                for (int v = 0; v < 25; v++) {
                    float xvv = xrow[v];
                    float4 a4 = *(const float4*)(adp + v * 28 + q * 4);
                    oq.x += xvv * a4.x; oq.y += xvv * a4.y;
                    oq.z += xvv * a4.z; oq.w += xvv * a4.w;
                }
                int w = q * 4;
                zrow[w] = oq.x;
                if (w + 1 < 25) zrow[w + 1] = oq.y;
                if (w + 2 < 25) zrow[w + 2] = oq.z;
                if (w + 3 < 25) zrow[w + 3] = oq.w;
            }
        }
        __syncthreads();
        // GEMM accumulate: acc[o-frag][col-frag] += wds[k][o] * zt[k][col]
#pragma unroll
        for (int k = 0; k < 24; k++) {
            float4 a0 = *(const float4*)&wds[k * 64 + ty * 8];
            float4 a1 = *(const float4*)&wds[k * 64 + ty * 8 + 4];
            float4 b0 = *(const float4*)&zt[k * 256 + tx * 8];
            float4 b1 = *(const float4*)&zt[k * 256 + tx * 8 + 4];
            float av[8] = {a0.x, a0.y, a0.z, a0.w, a1.x, a1.y, a1.z, a1.w};
            float bv[8] = {b0.x, b0.y, b0.z, b0.w, b1.x, b1.y, b1.z, b1.w};
#pragma unroll
            for (int r = 0; r < 8; r++)
#pragma unroll
                for (int j = 0; j < 8; j++) acc[r][j] += av[r] * bv[j];
        }
    }
    // epilogue: bias, store y, fused BN partial stats
#pragma unroll
    for (int rr = 0; rr < 8; rr++) {
        int o = ty * 8 + rr;
        float bias = g_bdsum[o];
        float* yr = g_y + (size_t)(n * Cc + o) * TV + t0 * 25;
        float s1 = 0.f, s2 = 0.f;
#pragma unroll
        for (int jp = 0; jp < 4; jp++) {
            int col = tx * 8 + jp * 2;
            if (col < 250) {
                float u0 = acc[rr][jp * 2] + bias;
                float u1 = acc[rr][jp * 2 + 1] + bias;
                *(float2*)(yr + col) = make_float2(u0, u1);
                s1 += u0 + u1;
                s2 += u0 * u0 + u1 * u1;
            }
        }
#pragma unroll
        for (int d = 16; d > 0; d >>= 1) {
            s1 += __shfl_xor_sync(0xffffffffu, s1, d);
            s2 += __shfl_xor_sync(0xffffffffu, s2, d);
        }
        if (tx == 0) {
            atomicAdd(&g_stats[o], s1);
            atomicAdd(&g_stats[64 + o], s2);
        }
    }
}

// ---------------- K4: normalize + gamma/beta + residual + relu ----------------
__global__ void k_final(const float* __restrict__ x,
                        const float* __restrict__ gamma, const float* __restrict__ beta,
                        float* __restrict__ out) {
    int i4 = blockIdx.x * 256 + threadIdx.x;        // 7,680,000 float4s
    int c = (i4 / 1875) & 63;                        // TV/4 = 1875
    float s1 = g_stats[c], s2 = g_stats[64 + c];
    float mean = s1 / CNT_BN;
    float var = s2 / CNT_BN - mean * mean;
    float scale = gamma[c] * rsqrtf(var + EPS_BN);
    float bet = beta[c];
    float4 yv = ((const float4*)g_y)[i4];
    float4 xv = ((const float4*)x)[i4];
    float4 o;
    o.x = fmaxf(0.f, (yv.x - mean) * scale + bet + xv.x);
    o.y = fmaxf(0.f, (yv.y - mean) * scale + bet + xv.y);
    o.z = fmaxf(0.f, (yv.z - mean) * scale + bet + xv.z);
    o.w = fmaxf(0.f, (yv.w - mean) * scale + bet + xv.w);
    ((float4*)out)[i4] = o;
}

// ---------------- launch ------------------------------------------------------
extern "C" void kernel_launch(void* const* d_in, const int* in_sizes, int n_in,
                              void* d_out, int out_size) {
    const float* x     = (const float*)d_in[0];
    const float* A     = (const float*)d_in[1];
    const float* W     = (const float*)d_in[2];
    const float* wa    = (const float*)d_in[3];
    const float* ba    = (const float*)d_in[4];
    const float* wb    = (const float*)d_in[5];
    const float* bb    = (const float*)d_in[6];
    const float* wd    = (const float*)d_in[7];
    const float* bd    = (const float*)d_in[8];
    const float* gamma = (const float*)d_in[9];
    const float* beta  = (const float*)d_in[10];
    float* out = (float*)d_out;

    static bool attr_set = false;
    if (!attr_set) {
        cudaFuncSetAttribute(k_attn, cudaFuncAttributeMaxDynamicSharedMemorySize, 84 * 1024);
        attr_set = true;
    }

    k_prep<<<472, 256>>>(wd, bd);
    k_attn<<<dim3(NS, 3), 256, 20625 * sizeof(float)>>>(x, wa, ba, wb, bb);
    k_softmax<<<NS, 32>>>(A, W);
    k_fused<<<dim3(Nn, 30), 256>>>(x);
    k_final<<<30000, 256>>>(x, gamma, beta, out);
}

// round 7
// speedup vs baseline: 1.1222x; 1.0773x over previous
#include <cuda_runtime.h>
#include <cstdint>

// Problem constants
#define Nn 64
#define Cc 64
#define Tt 300
#define Vv 25
#define Ss 3
#define TV 7500
#define NS 192
#define CNT_BN 480000.0f
#define EPS_BN 1e-5f

// ---------------- scratch -----------------------------------------------------
__device__ float g_scores[NS * 625];
__device__ float g_adapt[NS * 700];               // [ns][v][w pad 28]
__device__ float g_y[(size_t)Nn * Cc * TV];
__device__ float g_bdsum[Cc];
__device__ float g_stats[2 * Cc];

// ---------------- K0: prep ----------------------------------------------------
__global__ void k_prep(const float* __restrict__ wd, const float* __restrict__ bd) {
    int idx = blockIdx.x * 256 + threadIdx.x;
    if (idx < NS * 625) g_scores[idx] = 0.f;
    if (idx < Cc) g_bdsum[idx] = bd[idx] + bd[64 + idx] + bd[128 + idx];
    if (idx < 2 * Cc) g_stats[idx] = 0.f;
}

// ---------------- K1: fused projection + score accumulation -------------------
__global__ void __launch_bounds__(256, 2)
k_attn(const float* __restrict__ x,
       const float* __restrict__ wa, const float* __restrict__ ba,
       const float* __restrict__ wb, const float* __restrict__ bb) {
    extern __shared__ float sm[];
    float* wab  = sm;                   // [64 c][32 row]
    float* ab   = sm + 2048;            // [32 row][20 t' * 28]
    float* gsm  = sm + 2048 + 17920;    // [625]
    float* bias = gsm + 625;            // [32]

    int ns = blockIdx.x;
    int n = ns / Ss, s = ns - n * Ss;
    int tid = threadIdx.x;

    for (int j = tid; j < 2048; j += 256) {
        int c = j >> 5, row = j & 31;
        wab[c * 32 + row] = (row < 16) ? wa[(s * 16 + row) * 64 + c]
                                       : wb[(s * 16 + row - 16) * 64 + c];
    }
    if (tid < 32) bias[tid] = (tid < 16) ? ba[s * 16 + tid] : bb[s * 16 + tid - 16];
    for (int j = tid; j < 625; j += 256) gsm[j] = 0.f;
    for (int j = tid; j < 1920; j += 256) {
        int row = j / 60, rem = j - row * 60;
        ab[row * 560 + (rem / 3) * 28 + 25 + rem % 3] = 0.f;
    }
    __syncthreads();

    int rg = tid / 63, cg = tid - rg * 63;
    bool pact = (tid < 252);
    int tq = tid / 49, item = tid - tq * 49;
    bool sact = (tid < 196);
    int v0 = (item / 7) * 4, w0 = (item % 7) * 4;

    float greg[16];
#pragma unroll
    for (int r = 0; r < 16; r++) greg[r] = 0.f;

    const float* xn = x + (size_t)n * Cc * TV;
    int twchunk = blockIdx.y * 2500;

    for (int b = 0; b < 5; b++) {
        int twbase = twchunk + b * 500;
        float acc[8][8];
        if (pact) {
#pragma unroll
            for (int r = 0; r < 8; r++)
#pragma unroll
                for (int j = 0; j < 8; j++) acc[r][j] = 0.f;
            int colb = cg * 8;
            const float* xcol = xn + twbase + colb;
            bool m1 = (colb + 4 < 500);
            for (int k = 0; k < 64; k++) {
                float4 a0 = *(const float4*)&wab[k * 32 + rg * 8];
                float4 a1 = *(const float4*)&wab[k * 32 + rg * 8 + 4];
                const float* xr = xcol + (size_t)k * TV;
                float4 b0 = *(const float4*)xr;
                float4 b1 = m1 ? *(const float4*)(xr + 4) : make_float4(0.f, 0.f, 0.f, 0.f);
                float av[8] = {a0.x, a0.y, a0.z, a0.w, a1.x, a1.y, a1.z, a1.w};
                float bv[8] = {b0.x, b0.y, b0.z, b0.w, b1.x, b1.y, b1.z, b1.w};
#pragma unroll
                for (int r = 0; r < 8; r++)
#pragma unroll
                    for (int j = 0; j < 8; j++) acc[r][j] += av[r] * bv[j];
            }
#pragma unroll
            for (int j = 0; j < 8; j++) {
                int col = colb + j;
                if (col < 500) {
                    int tp = col / 25, v = col - tp * 25;
#pragma unroll
                    for (int r = 0; r < 8; r++) {
                        int row = rg * 8 + r;
                        ab[row * 560 + tp * 28 + v] = acc[r][j] + bias[row];
                    }
                }
            }
        }
        __syncthreads();
        if (sact) {
#pragma unroll
            for (int i4 = 0; i4 < 4; i4++) {
                const float* ia = ab + (tq * 4 + i4) * 560;
                const float* ib = ab + (16 + tq * 4 + i4) * 560;
                for (int tp = 0; tp < 20; tp++) {
                    float4 av = *(const float4*)(ia + tp * 28 + v0);
                    float4 bv = *(const float4*)(ib + tp * 28 + w0);
                    greg[0]  += av.x * bv.x; greg[1]  += av.x * bv.y; greg[2]  += av.x * bv.z; greg[3]  += av.x * bv.w;
                    greg[4]  += av.y * bv.x; greg[5]  += av.y * bv.y; greg[6]  += av.y * bv.z; greg[7]  += av.y * bv.w;
                    greg[8]  += av.z * bv.x; greg[9]  += av.z * bv.y; greg[10] += av.z * bv.z; greg[11] += av.z * bv.w;
                    greg[12] += av.w * bv.x; greg[13] += av.w * bv.y; greg[14] += av.w * bv.z; greg[15] += av.w * bv.w;
                }
            }
        }
        __syncthreads();
    }
    if (sact) {
#pragma unroll
        for (int r = 0; r < 4; r++)
#pragma unroll
            for (int cix = 0; cix < 4; cix++) {
                int v = v0 + r, w = w0 + cix;
                if (v < Vv && w < Vv) atomicAdd(&gsm[v * 25 + w], greg[r * 4 + cix]);
            }
    }
    __syncthreads();
    for (int j = tid; j < 625; j += 256) atomicAdd(&g_scores[ns * 625 + j], gsm[j]);
}

// ---------------- K2: softmax + adapt (padded 28) -----------------------------
__global__ void k_softmax(const float* __restrict__ A, const float* __restrict__ W) {
    int ns = blockIdx.x;
    int s = ns % Ss;
    int w = threadIdx.x;
    if (w >= 28) return;
    if (w >= Vv) {
#pragma unroll
        for (int v = 0; v < Vv; v++) g_adapt[ns * 700 + v * 28 + w] = 0.f;
        return;
    }
    float col[Vv];
    const float inv = 1.f / 4800.f;
    float m = -1e30f;
#pragma unroll
    for (int v = 0; v < Vv; v++) {
        col[v] = g_scores[ns * 625 + v * 25 + w] * inv;
        m = fmaxf(m, col[v]);
    }
    float sum = 0.f;
#pragma unroll
    for (int v = 0; v < Vv; v++) { col[v] = __expf(col[v] - m); sum += col[v]; }
    float r = 1.f / sum;
#pragma unroll
    for (int v = 0; v < Vv; v++) {
        int off = s * 625 + v * 25 + w;
        g_adapt[ns * 700 + v * 28 + w] = A[off] + W[off] + col[v] * r;
    }
}

// ---------------- K3: fused z (fp32) + tf32 mma.sync GEMM + BN stats ----------
// grid (64, 30): (n, 10-t tile -> 250 cols). block 256 = 8 warps.
// GEMM: D[64 o, 256 col] += A[64 o, 24 k] * B[24 k, 256 col] per chunk (8 chunks).
// Warp (otile = wid&3, nhalf = wid>>2) owns m16 x n128 -> 16 mma n-tiles.
__global__ void __launch_bounds__(256, 2)
k_fused_mma(const float* __restrict__ x, const float* __restrict__ wd) {
    __shared__ float ad3[2100];        // [s][v][28]
    __shared__ float pool[9904];       // xs[2000] | zt[24*260] | wds[64*26]; ysm[64*132] overlaps
    float* xs  = pool;                 // [cc][250]
    float* zt  = pool + 2000;          // [k][col pad 260]
    float* wds = pool + 8240;          // [o][k pad 26]
    float* ysm = pool;                 // epilogue staging

    int n = blockIdx.x;
    int t0 = blockIdx.y * 10;          // 250 cols
    int tid = threadIdx.x;
    int wid = tid >> 5, lane = tid & 31;
    int gID = lane >> 2, tig = lane & 3;

    for (int j = tid; j < 2100; j += 256) ad3[j] = g_adapt[n * 2100 + j];

    float d[16][4];
#pragma unroll
    for (int nt = 0; nt < 16; nt++)
#pragma unroll
        for (int e = 0; e < 4; e++) d[nt][e] = 0.f;

    // z-compute mapping: 240 threads = (zs 0..2, zc 0..7, ztt 0..9)
    int zs = tid / 80;
    int zr = tid - zs * 80;
    int zc = zr / 10, ztt = zr - zc * 10;
    bool zact = (tid < 240);

    int otile = wid & 3, nhalf = wid >> 2;
    int col0 = nhalf * 128;

    for (int c = 0; c < 8; c++) {
        int c0 = c * 8;
        __syncthreads();   // previous chunk's mma LDS reads done
        // load x tile [8 cc][250]
        for (int j = tid; j < 2000; j += 256) {
            int cc = j / 250, j2 = j - cc * 250;
            xs[cc * 250 + j2] = x[(size_t)(n * Cc + c0 + cc) * TV + t0 * 25 + j2];
        }
        // load A chunk: wds[o][kk], kk = s*8+cc -> wd[(s*64+o)*64 + c0+cc]
        for (int j = tid; j < 1536; j += 256) {
            int o = j / 24, kk = j - o * 24;
            int s = kk >> 3, cc = kk & 7;
            wds[o * 26 + kk] = wd[(size_t)((s << 6) + o) * 64 + c0 + cc];
        }
        __syncthreads();
        // z-compute: zt[krow][ztt*25+w] = sum_v xs[zc][ztt*25+v] * ad3[zs][v][w]
        if (zact) {
            int krow = zs * 8 + zc;
            const float* xrow = xs + zc * 250 + ztt * 25;
            const float* adp = ad3 + zs * 700;
            float xv[25];
#pragma unroll
            for (int v = 0; v < 25; v++) xv[v] = xrow[v];
            float* zrow = zt + krow * 260 + ztt * 25;
#pragma unroll
            for (int q = 0; q < 7; q++) {
                float4 o4 = make_float4(0.f, 0.f, 0.f, 0.f);
#pragma unroll
                for (int v = 0; v < 25; v++) {
                    float4 a4 = *(const float4*)(adp + v * 28 + q * 4);
                    o4.x += xv[v] * a4.x; o4.y += xv[v] * a4.y;
                    o4.z += xv[v] * a4.z; o4.w += xv[v] * a4.w;
                }
                int wb = q * 4;
                zrow[wb] = o4.x;
                if (wb + 1 < 25) zrow[wb + 1] = o4.y;
                if (wb + 2 < 25) zrow[wb + 2] = o4.z;
                if (wb + 3 < 25) zrow[wb + 3] = o4.w;
            }
        }
        __syncthreads();   // zt + wds ready
        // tf32 mma: 3 k-steps of 8
#pragma unroll
        for (int ks = 0; ks < 3; ks++) {
            int k0 = ks * 8;
            int arow = otile * 16 + gID;
            uint32_t a0 = __float_as_uint(wds[arow * 26 + k0 + tig]);
            uint32_t a1 = __float_as_uint(wds[(arow + 8) * 26 + k0 + tig]);
            uint32_t a2 = __float_as_uint(wds[arow * 26 + k0 + 4 + tig]);
            uint32_t a3 = __float_as_uint(wds[(arow + 8) * 26 + k0 + 4 + tig]);
#pragma unroll
            for (int nt = 0; nt < 16; nt++) {
                int nc = col0 + nt * 8 + gID;
                uint32_t b0 = __float_as_uint(zt[(k0 + tig) * 260 + nc]);
                uint32_t b1 = __float_as_uint(zt[(k0 + 4 + tig) * 260 + nc]);
                asm volatile(
                    "mma.sync.aligned.m16n8k8.row.col.f32.tf32.tf32.f32 "
                    "{%0,%1,%2,%3}, {%4,%5,%6,%7}, {%8,%9}, {%0,%1,%2,%3};"
                    : "+f"(d[nt][0]), "+f"(d[nt][1]), "+f"(d[nt][2]), "+f"(d[nt][3])
                    : "r"(a0), "r"(a1), "r"(a2), "r"(a3), "r"(b0), "r"(b1));
            }
        }
    }

    // epilogue in two 128-col halves: stage D to ysm, coalesced store + BN stats
#pragma unroll 1
    for (int h = 0; h < 2; h++) {
        __syncthreads();
        if (nhalf == h) {
#pragma unroll
            for (int nt = 0; nt < 16; nt++) {
                int colb = nt * 8 + tig * 2;
                int r0 = otile * 16 + gID;
                ysm[r0 * 132 + colb]           = d[nt][0];
                ysm[r0 * 132 + colb + 1]       = d[nt][1];
                ysm[(r0 + 8) * 132 + colb]     = d[nt][2];
                ysm[(r0 + 8) * 132 + colb + 1] = d[nt][3];
            }
        }
        __syncthreads();
        int ncols = h ? 122 : 128;
#pragma unroll 1
        for (int rr = 0; rr < 8; rr++) {
            int o = wid * 8 + rr;
            float bias = g_bdsum[o];
            float s1 = 0.f, s2 = 0.f;
            float* yp = g_y + (size_t)(n * Cc + o) * TV + t0 * 25 + h * 128;
            for (int col = lane; col < ncols; col += 32) {
                float v = ysm[o * 132 + col] + bias;
                yp[col] = v;
                s1 += v; s2 += v * v;
            }
#pragma unroll
            for (int dd = 16; dd > 0; dd >>= 1) {
                s1 += __shfl_xor_sync(0xffffffffu, s1, dd);
                s2 += __shfl_xor_sync(0xffffffffu, s2, dd);
            }
            if (lane == 0) {
                atomicAdd(&g_stats[o], s1);
                atomicAdd(&g_stats[64 + o], s2);
            }
        }
    }
}

// ---------------- K4: normalize + gamma/beta + residual + relu ----------------
__global__ void k_final(const float* __restrict__ x,
                        const float* __restrict__ gamma, const float* __restrict__ beta,
                        float* __restrict__ out) {
    int i4 = blockIdx.x * 256 + threadIdx.x;
    int c = (i4 / 1875) & 63;
    float s1 = g_stats[c], s2 = g_stats[64 + c];
    float mean = s1 / CNT_BN;
    float var = s2 / CNT_BN - mean * mean;
    float scale = gamma[c] * rsqrtf(var + EPS_BN);
    float bet = beta[c];
    float4 yv = ((const float4*)g_y)[i4];
    float4 xv = ((const float4*)x)[i4];
    float4 o;
    o.x = fmaxf(0.f, (yv.x - mean) * scale + bet + xv.x);
    o.y = fmaxf(0.f, (yv.y - mean) * scale + bet + xv.y);
    o.z = fmaxf(0.f, (yv.z - mean) * scale + bet + xv.z);
    o.w = fmaxf(0.f, (yv.w - mean) * scale + bet + xv.w);
    ((float4*)out)[i4] = o;
}

// ---------------- launch ------------------------------------------------------
extern "C" void kernel_launch(void* const* d_in, const int* in_sizes, int n_in,
                              void* d_out, int out_size) {
    const float* x     = (const float*)d_in[0];
    const float* A     = (const float*)d_in[1];
    const float* W     = (const float*)d_in[2];
    const float* wa    = (const float*)d_in[3];
    const float* ba    = (const float*)d_in[4];
    const float* wb    = (const float*)d_in[5];
    const float* bb    = (const float*)d_in[6];
    const float* wd    = (const float*)d_in[7];
    const float* bd    = (const float*)d_in[8];
    const float* gamma = (const float*)d_in[9];
    const float* beta  = (const float*)d_in[10];
    float* out = (float*)d_out;

    static bool attr_set = false;
    if (!attr_set) {
        cudaFuncSetAttribute(k_attn, cudaFuncAttributeMaxDynamicSharedMemorySize, 84 * 1024);
        attr_set = true;
    }

    k_prep<<<472, 256>>>(wd, bd);
    k_attn<<<dim3(NS, 3), 256, 20625 * sizeof(float)>>>(x, wa, ba, wb, bb);
    k_softmax<<<NS, 32>>>(A, W);
    k_fused_mma<<<dim3(Nn, 30), 256>>>(x, wd);
    k_final<<<30000, 256>>>(x, gamma, beta, out);
}

// round 8
// speedup vs baseline: 1.1630x; 1.0363x over previous
#include <cuda_runtime.h>
#include <cstdint>

// Problem constants
#define Nn 64
#define Cc 64
#define Tt 300
#define Vv 25
#define Ss 3
#define TV 7500
#define NS 192
#define CNT_BN 480000.0f
#define EPS_BN 1e-5f

// ---------------- scratch -----------------------------------------------------
__device__ float g_scores[NS * 625];
__device__ float g_adapt[NS * 700];               // [ns][v][w pad 28]
__device__ float g_y[(size_t)Nn * Cc * TV];
__device__ float g_bdsum[Cc];
__device__ float g_stats[2 * Cc];

// ---------------- K0: prep ----------------------------------------------------
__global__ void k_prep(const float* __restrict__ wd, const float* __restrict__ bd) {
    int idx = blockIdx.x * 256 + threadIdx.x;
    if (idx < NS * 625) g_scores[idx] = 0.f;
    if (idx < Cc) g_bdsum[idx] = bd[idx] + bd[64 + idx] + bd[128 + idx];
    if (idx < 2 * Cc) g_stats[idx] = 0.f;
}

// ---------------- K1: fused projection + score accumulation -------------------
__global__ void __launch_bounds__(256, 2)
k_attn(const float* __restrict__ x,
       const float* __restrict__ wa, const float* __restrict__ ba,
       const float* __restrict__ wb, const float* __restrict__ bb) {
    extern __shared__ float sm[];
    float* wab  = sm;                   // [64 c][32 row]
    float* ab   = sm + 2048;            // [32 row][20 t' * 28]
    float* gsm  = sm + 2048 + 17920;    // [625]
    float* bias = gsm + 625;            // [32]

    int ns = blockIdx.x;
    int n = ns / Ss, s = ns - n * Ss;
    int tid = threadIdx.x;

    for (int j = tid; j < 2048; j += 256) {
        int c = j >> 5, row = j & 31;
        wab[c * 32 + row] = (row < 16) ? wa[(s * 16 + row) * 64 + c]
                                       : wb[(s * 16 + row - 16) * 64 + c];
    }
    if (tid < 32) bias[tid] = (tid < 16) ? ba[s * 16 + tid] : bb[s * 16 + tid - 16];
    for (int j = tid; j < 625; j += 256) gsm[j] = 0.f;
    for (int j = tid; j < 1920; j += 256) {
        int row = j / 60, rem = j - row * 60;
        ab[row * 560 + (rem / 3) * 28 + 25 + rem % 3] = 0.f;
    }
    __syncthreads();

    int rg = tid / 63, cg = tid - rg * 63;
    bool pact = (tid < 252);
    int tq = tid / 49, item = tid - tq * 49;
    bool sact = (tid < 196);
    int v0 = (item / 7) * 4, w0 = (item % 7) * 4;

    float greg[16];
#pragma unroll
    for (int r = 0; r < 16; r++) greg[r] = 0.f;

    const float* xn = x + (size_t)n * Cc * TV;
    int twchunk = blockIdx.y * 2500;

    for (int b = 0; b < 5; b++) {
        int twbase = twchunk + b * 500;
        float acc[8][8];
        if (pact) {
#pragma unroll
            for (int r = 0; r < 8; r++)
#pragma unroll
                for (int j = 0; j < 8; j++) acc[r][j] = 0.f;
            int colb = cg * 8;
            const float* xcol = xn + twbase + colb;
            bool m1 = (colb + 4 < 500);
            for (int k = 0; k < 64; k++) {
                float4 a0 = *(const float4*)&wab[k * 32 + rg * 8];
                float4 a1 = *(const float4*)&wab[k * 32 + rg * 8 + 4];
                const float* xr = xcol + (size_t)k * TV;
                float4 b0 = *(const float4*)xr;
                float4 b1 = m1 ? *(const float4*)(xr + 4) : make_float4(0.f, 0.f, 0.f, 0.f);
                float av[8] = {a0.x, a0.y, a0.z, a0.w, a1.x, a1.y, a1.z, a1.w};
                float bv[8] = {b0.x, b0.y, b0.z, b0.w, b1.x, b1.y, b1.z, b1.w};
#pragma unroll
                for (int r = 0; r < 8; r++)
#pragma unroll
                    for (int j = 0; j < 8; j++) acc[r][j] += av[r] * bv[j];
            }
#pragma unroll
            for (int j = 0; j < 8; j++) {
                int col = colb + j;
                if (col < 500) {
                    int tp = col / 25, v = col - tp * 25;
#pragma unroll
                    for (int r = 0; r < 8; r++) {
                        int row = rg * 8 + r;
                        ab[row * 560 + tp * 28 + v] = acc[r][j] + bias[row];
                    }
                }
            }
        }
        __syncthreads();
        if (sact) {
#pragma unroll
            for (int i4 = 0; i4 < 4; i4++) {
                const float* ia = ab + (tq * 4 + i4) * 560;
                const float* ib = ab + (16 + tq * 4 + i4) * 560;
                for (int tp = 0; tp < 20; tp++) {
                    float4 av = *(const float4*)(ia + tp * 28 + v0);
                    float4 bv = *(const float4*)(ib + tp * 28 + w0);
                    greg[0]  += av.x * bv.x; greg[1]  += av.x * bv.y; greg[2]  += av.x * bv.z; greg[3]  += av.x * bv.w;
                    greg[4]  += av.y * bv.x; greg[5]  += av.y * bv.y; greg[6]  += av.y * bv.z; greg[7]  += av.y * bv.w;
                    greg[8]  += av.z * bv.x; greg[9]  += av.z * bv.y; greg[10] += av.z * bv.z; greg[11] += av.z * bv.w;
                    greg[12] += av.w * bv.x; greg[13] += av.w * bv.y; greg[14] += av.w * bv.z; greg[15] += av.w * bv.w;
                }
            }
        }
        __syncthreads();
    }
    if (sact) {
#pragma unroll
        for (int r = 0; r < 4; r++)
#pragma unroll
            for (int cix = 0; cix < 4; cix++) {
                int v = v0 + r, w = w0 + cix;
                if (v < Vv && w < Vv) atomicAdd(&gsm[v * 25 + w], greg[r * 4 + cix]);
            }
    }
    __syncthreads();
    for (int j = tid; j < 625; j += 256) atomicAdd(&g_scores[ns * 625 + j], gsm[j]);
}

// ---------------- K2: softmax + adapt (padded 28) -----------------------------
__global__ void k_softmax(const float* __restrict__ A, const float* __restrict__ W) {
    int ns = blockIdx.x;
    int s = ns % Ss;
    int w = threadIdx.x;
    if (w >= 28) return;
    if (w >= Vv) {
#pragma unroll
        for (int v = 0; v < Vv; v++) g_adapt[ns * 700 + v * 28 + w] = 0.f;
        return;
    }
    float col[Vv];
    const float inv = 1.f / 4800.f;
    float m = -1e30f;
#pragma unroll
    for (int v = 0; v < Vv; v++) {
        col[v] = g_scores[ns * 625 + v * 25 + w] * inv;
        m = fmaxf(m, col[v]);
    }
    float sum = 0.f;
#pragma unroll
    for (int v = 0; v < Vv; v++) { col[v] = __expf(col[v] - m); sum += col[v]; }
    float r = 1.f / sum;
#pragma unroll
    for (int v = 0; v < Vv; v++) {
        int off = s * 625 + v * 25 + w;
        g_adapt[ns * 700 + v * 28 + w] = A[off] + W[off] + col[v] * r;
    }
}

// ---------------- K3: fused z (fp32) + tf32 mma.sync, 1-barrier pipeline ------
// grid (64, 30): (n, 10-t tile -> 250 cols). block 256 = 8 warps.
// Dynamic smem pool (floats):
//   xs  2 x 2000  @ 0       (x tiles, double buffered)
//   zt  2 x 6336  @ 4000    ([k][col pad 264], conflict-free B reads)
//   wds 2 x 1664  @ 16672   ([o][k pad 26])
//   ad3 2100      @ 20000
//   ysm 64 x 132  @ 0       (epilogue, aliases xs/zt)
#define FM_SMEM_FLOATS 22100
__global__ void __launch_bounds__(256, 2)
k_fused_mma(const float* __restrict__ x, const float* __restrict__ wd) {
    extern __shared__ float dsm[];
    float* ad3 = dsm + 20000;
    float* ysm = dsm;

    int n = blockIdx.x;
    int t0 = blockIdx.y * 10;          // 250 cols
    int tid = threadIdx.x;
    int wid = tid >> 5, lane = tid & 31;
    int gID = lane >> 2, tig = lane & 3;

    float d[16][4];
#pragma unroll
    for (int nt = 0; nt < 16; nt++)
#pragma unroll
        for (int e = 0; e < 4; e++) d[nt][e] = 0.f;

    // z-compute mapping: 240 threads = (zs 0..2, zc 0..7, ztt 0..9)
    int zs = tid / 80;
    int zr = tid - zs * 80;
    int zc = zr / 10, ztt = zr - zc * 10;
    bool zact = (tid < 240);

    int otile = wid & 3, nhalf = wid >> 2;
    int col0 = nhalf * 128;

    // ---- prologue: ad3 + chunk-0 xs/wds ----
    for (int j = tid; j < 2100; j += 256) ad3[j] = g_adapt[n * 2100 + j];
    for (int j = tid; j < 1000; j += 256) {
        int cc = j / 125, j2 = j - cc * 125;
        *(float2*)&dsm[cc * 250 + j2 * 2] =
            *(const float2*)(x + (size_t)(n * Cc + cc) * TV + t0 * 25 + j2 * 2);
    }
    for (int j = tid; j < 1536; j += 256) {
        int o = j / 24, kk = j - o * 24;
        int s = kk >> 3, cc = kk & 7;
        dsm[16672 + o * 26 + kk] = wd[(size_t)((s << 6) + o) * 64 + cc];
    }
    __syncthreads();

    for (int c = 0; c < 8; c++) {
        int buf = c & 1, nbuf = buf ^ 1;
        float* xsb = dsm + buf * 2000;
        float* xsn = dsm + nbuf * 2000;
        float* ztb = dsm + 4000 + buf * 6336;
        float* wdb = dsm + 16672 + buf * 1664;
        float* wdn = dsm + 16672 + nbuf * 1664;

        // ---- phase 1: load next x tile; z-compute(c) ----
        if (c < 7) {
            int c0n = (c + 1) * 8;
            for (int j = tid; j < 1000; j += 256) {
                int cc = j / 125, j2 = j - cc * 125;
                *(float2*)&xsn[cc * 250 + j2 * 2] =
                    *(const float2*)(x + (size_t)(n * Cc + c0n + cc) * TV + t0 * 25 + j2 * 2);
            }
        }
        if (zact) {
            int krow = zs * 8 + zc;
            const float* xrow = xsb + zc * 250 + ztt * 25;
            const float* adp = ad3 + zs * 700;
            float xv[25];
#pragma unroll
            for (int v = 0; v < 25; v++) xv[v] = xrow[v];
            float* zrow = ztb + krow * 264 + ztt * 25;
#pragma unroll
            for (int q = 0; q < 7; q++) {
                // two partial chains (even/odd v) per component -> 8 independent chains
                float4 ea = make_float4(0.f, 0.f, 0.f, 0.f);
                float4 eb = make_float4(0.f, 0.f, 0.f, 0.f);
#pragma unroll
                for (int v = 0; v < 24; v += 2) {
                    float4 a0 = *(const float4*)(adp + v * 28 + q * 4);
                    float4 a1 = *(const float4*)(adp + (v + 1) * 28 + q * 4);
                    ea.x += xv[v] * a0.x;     ea.y += xv[v] * a0.y;
                    ea.z += xv[v] * a0.z;     ea.w += xv[v] * a0.w;
                    eb.x += xv[v + 1] * a1.x; eb.y += xv[v + 1] * a1.y;
                    eb.z += xv[v + 1] * a1.z; eb.w += xv[v + 1] * a1.w;
                }
                {
                    float4 a24 = *(const float4*)(adp + 24 * 28 + q * 4);
                    ea.x += xv[24] * a24.x; ea.y += xv[24] * a24.y;
                    ea.z += xv[24] * a24.z; ea.w += xv[24] * a24.w;
                }
                int wb = q * 4;
                zrow[wb] = ea.x + eb.x;
                if (wb + 1 < 25) zrow[wb + 1] = ea.y + eb.y;
                if (wb + 2 < 25) zrow[wb + 2] = ea.z + eb.z;
                if (wb + 3 < 25) zrow[wb + 3] = ea.w + eb.w;
            }
        }
        __syncthreads();   // the ONLY barrier per chunk

        // ---- phase 2: load next wd tile; mma(c) ----
        if (c < 7) {
            int c0n = (c + 1) * 8;
            for (int j = tid; j < 1536; j += 256) {
                int o = j / 24, kk = j - o * 24;
                int s = kk >> 3, cc = kk & 7;
                wdn[o * 26 + kk] = wd[(size_t)((s << 6) + o) * 64 + c0n + cc];
            }
        }
#pragma unroll
        for (int ks = 0; ks < 3; ks++) {
            int k0 = ks * 8;
            int arow = otile * 16 + gID;
            uint32_t a0 = __float_as_uint(wdb[arow * 26 + k0 + tig]);
            uint32_t a1 = __float_as_uint(wdb[(arow + 8) * 26 + k0 + tig]);
            uint32_t a2 = __float_as_uint(wdb[arow * 26 + k0 + 4 + tig]);
            uint32_t a3 = __float_as_uint(wdb[(arow + 8) * 26 + k0 + 4 + tig]);
#pragma unroll
            for (int nt = 0; nt < 16; nt++) {
                int nc = col0 + nt * 8 + gID;
                uint32_t b0 = __float_as_uint(ztb[(k0 + tig) * 264 + nc]);
                uint32_t b1 = __float_as_uint(ztb[(k0 + 4 + tig) * 264 + nc]);
                asm volatile(
                    "mma.sync.aligned.m16n8k8.row.col.f32.tf32.tf32.f32 "
                    "{%0,%1,%2,%3}, {%4,%5,%6,%7}, {%8,%9}, {%0,%1,%2,%3};"
                    : "+f"(d[nt][0]), "+f"(d[nt][1]), "+f"(d[nt][2]), "+f"(d[nt][3])
                    : "r"(a0), "r"(a1), "r"(a2), "r"(a3), "r"(b0), "r"(b1));
            }
        }
    }

    // ---- epilogue in two 128-col halves ----
#pragma unroll 1
    for (int h = 0; h < 2; h++) {
        __syncthreads();
        if (nhalf == h) {
#pragma unroll
            for (int nt = 0; nt < 16; nt++) {
                int colb = nt * 8 + tig * 2;
                int r0 = otile * 16 + gID;
                ysm[r0 * 132 + colb]           = d[nt][0];
                ysm[r0 * 132 + colb + 1]       = d[nt][1];
                ysm[(r0 + 8) * 132 + colb]     = d[nt][2];
                ysm[(r0 + 8) * 132 + colb + 1] = d[nt][3];
            }
        }
        __syncthreads();
        int ncols = h ? 122 : 128;
#pragma unroll 1
        for (int rr = 0; rr < 8; rr++) {
            int o = wid * 8 + rr;
            float bias = g_bdsum[o];
            float s1 = 0.f, s2 = 0.f;
            float* yp = g_y + (size_t)(n * Cc + o) * TV + t0 * 25 + h * 128;
            for (int col = lane; col < ncols; col += 32) {
                float v = ysm[o * 132 + col] + bias;
                yp[col] = v;
                s1 += v; s2 += v * v;
            }
#pragma unroll
            for (int dd = 16; dd > 0; dd >>= 1) {
                s1 += __shfl_xor_sync(0xffffffffu, s1, dd);
                s2 += __shfl_xor_sync(0xffffffffu, s2, dd);
            }
            if (lane == 0) {
                atomicAdd(&g_stats[o], s1);
                atomicAdd(&g_stats[64 + o], s2);
            }
        }
    }
}

// ---------------- K4: normalize + gamma/beta + residual + relu ----------------
__global__ void k_final(const float* __restrict__ x,
                        const float* __restrict__ gamma, const float* __restrict__ beta,
                        float* __restrict__ out) {
    int i4 = blockIdx.x * 256 + threadIdx.x;
    int c = (i4 / 1875) & 63;
    float s1 = g_stats[c], s2 = g_stats[64 + c];
    float mean = s1 / CNT_BN;
    float var = s2 / CNT_BN - mean * mean;
    float scale = gamma[c] * rsqrtf(var + EPS_BN);
    float bet = beta[c];
    float4 yv = ((const float4*)g_y)[i4];
    float4 xv = ((const float4*)x)[i4];
    float4 o;
    o.x = fmaxf(0.f, (yv.x - mean) * scale + bet + xv.x);
    o.y = fmaxf(0.f, (yv.y - mean) * scale + bet + xv.y);
    o.z = fmaxf(0.f, (yv.z - mean) * scale + bet + xv.z);
    o.w = fmaxf(0.f, (yv.w - mean) * scale + bet + xv.w);
    ((float4*)out)[i4] = o;
}

// ---------------- launch ------------------------------------------------------
extern "C" void kernel_launch(void* const* d_in, const int* in_sizes, int n_in,
                              void* d_out, int out_size) {
    const float* x     = (const float*)d_in[0];
    const float* A     = (const float*)d_in[1];
    const float* W     = (const float*)d_in[2];
    const float* wa    = (const float*)d_in[3];
    const float* ba    = (const float*)d_in[4];
    const float* wb    = (const float*)d_in[5];
    const float* bb    = (const float*)d_in[6];
    const float* wd    = (const float*)d_in[7];
    const float* bd    = (const float*)d_in[8];
    const float* gamma = (const float*)d_in[9];
    const float* beta  = (const float*)d_in[10];
    float* out = (float*)d_out;

    static bool attr_set = false;
    if (!attr_set) {
        cudaFuncSetAttribute(k_attn, cudaFuncAttributeMaxDynamicSharedMemorySize, 84 * 1024);
        cudaFuncSetAttribute(k_fused_mma, cudaFuncAttributeMaxDynamicSharedMemorySize,
                             FM_SMEM_FLOATS * sizeof(float));
        attr_set = true;
    }

    k_prep<<<472, 256>>>(wd, bd);
    k_attn<<<dim3(NS, 3), 256, 20625 * sizeof(float)>>>(x, wa, ba, wb, bb);
    k_softmax<<<NS, 32>>>(A, W);
    k_fused_mma<<<dim3(Nn, 30), 256, FM_SMEM_FLOATS * sizeof(float)>>>(x, wd);
    k_final<<<30000, 256>>>(x, gamma, beta, out);
}

// round 9
// speedup vs baseline: 1.1690x; 1.0052x over previous
#include <cuda_runtime.h>
#include <cstdint>

// Problem constants
#define Nn 64
#define Cc 64
#define Tt 300
#define Vv 25
#define Ss 3
#define TV 7500
#define NS 192
#define CNT_BN 480000.0f
#define EPS_BN 1e-5f

// ---------------- scratch -----------------------------------------------------
__device__ float g_scores[NS * 625];
__device__ float g_adapt[NS * 700];               // [ns][v][w pad 28]
__device__ float g_y[(size_t)Nn * Cc * TV];
__device__ float g_bdsum[Cc];
__device__ float g_stats[2 * Cc];

// ---------------- K0: prep ----------------------------------------------------
__global__ void k_prep(const float* __restrict__ wd, const float* __restrict__ bd) {
    int idx = blockIdx.x * 256 + threadIdx.x;
    if (idx < NS * 625) g_scores[idx] = 0.f;
    if (idx < Cc) g_bdsum[idx] = bd[idx] + bd[64 + idx] + bd[128 + idx];
    if (idx < 2 * Cc) g_stats[idx] = 0.f;
}

// ---------------- K1: fused projection + score accumulation -------------------
__global__ void __launch_bounds__(256, 2)
k_attn(const float* __restrict__ x,
       const float* __restrict__ wa, const float* __restrict__ ba,
       const float* __restrict__ wb, const float* __restrict__ bb) {
    extern __shared__ float sm[];
    float* wab  = sm;                   // [64 c][32 row]
    float* ab   = sm + 2048;            // [32 row][20 t' * 28]
    float* gsm  = sm + 2048 + 17920;    // [625]
    float* bias = gsm + 625;            // [32]

    int ns = blockIdx.x;
    int n = ns / Ss, s = ns - n * Ss;
    int tid = threadIdx.x;

    for (int j = tid; j < 2048; j += 256) {
        int c = j >> 5, row = j & 31;
        wab[c * 32 + row] = (row < 16) ? wa[(s * 16 + row) * 64 + c]
                                       : wb[(s * 16 + row - 16) * 64 + c];
    }
    if (tid < 32) bias[tid] = (tid < 16) ? ba[s * 16 + tid] : bb[s * 16 + tid - 16];
    for (int j = tid; j < 625; j += 256) gsm[j] = 0.f;
    for (int j = tid; j < 1920; j += 256) {
        int row = j / 60, rem = j - row * 60;
        ab[row * 560 + (rem / 3) * 28 + 25 + rem % 3] = 0.f;
    }
    __syncthreads();

    int rg = tid / 63, cg = tid - rg * 63;
    bool pact = (tid < 252);
    int tq = tid / 49, item = tid - tq * 49;
    bool sact = (tid < 196);
    int v0 = (item / 7) * 4, w0 = (item % 7) * 4;

    float greg[16];
#pragma unroll
    for (int r = 0; r < 16; r++) greg[r] = 0.f;

    const float* xn = x + (size_t)n * Cc * TV;
    int twchunk = blockIdx.y * 2500;

    for (int b = 0; b < 5; b++) {
        int twbase = twchunk + b * 500;
        float acc[8][8];
        if (pact) {
#pragma unroll
            for (int r = 0; r < 8; r++)
#pragma unroll
                for (int j = 0; j < 8; j++) acc[r][j] = 0.f;
            int colb = cg * 8;
            const float* xcol = xn + twbase + colb;
            bool m1 = (colb + 4 < 500);
            for (int k = 0; k < 64; k++) {
                float4 a0 = *(const float4*)&wab[k * 32 + rg * 8];
                float4 a1 = *(const float4*)&wab[k * 32 + rg * 8 + 4];
                const float* xr = xcol + (size_t)k * TV;
                float4 b0 = *(const float4*)xr;
                float4 b1 = m1 ? *(const float4*)(xr + 4) : make_float4(0.f, 0.f, 0.f, 0.f);
                float av[8] = {a0.x, a0.y, a0.z, a0.w, a1.x, a1.y, a1.z, a1.w};
                float bv[8] = {b0.x, b0.y, b0.z, b0.w, b1.x, b1.y, b1.z, b1.w};
#pragma unroll
                for (int r = 0; r < 8; r++)
#pragma unroll
                    for (int j = 0; j < 8; j++) acc[r][j] += av[r] * bv[j];
            }
#pragma unroll
            for (int j = 0; j < 8; j++) {
                int col = colb + j;
                if (col < 500) {
                    int tp = col / 25, v = col - tp * 25;
#pragma unroll
                    for (int r = 0; r < 8; r++) {
                        int row = rg * 8 + r;
                        ab[row * 560 + tp * 28 + v] = acc[r][j] + bias[row];
                    }
                }
            }
        }
        __syncthreads();
        if (sact) {
#pragma unroll
            for (int i4 = 0; i4 < 4; i4++) {
                const float* ia = ab + (tq * 4 + i4) * 560;
                const float* ib = ab + (16 + tq * 4 + i4) * 560;
                for (int tp = 0; tp < 20; tp++) {
                    float4 av = *(const float4*)(ia + tp * 28 + v0);
                    float4 bv = *(const float4*)(ib + tp * 28 + w0);
                    greg[0]  += av.x * bv.x; greg[1]  += av.x * bv.y; greg[2]  += av.x * bv.z; greg[3]  += av.x * bv.w;
                    greg[4]  += av.y * bv.x; greg[5]  += av.y * bv.y; greg[6]  += av.y * bv.z; greg[7]  += av.y * bv.w;
                    greg[8]  += av.z * bv.x; greg[9]  += av.z * bv.y; greg[10] += av.z * bv.z; greg[11] += av.z * bv.w;
                    greg[12] += av.w * bv.x; greg[13] += av.w * bv.y; greg[14] += av.w * bv.z; greg[15] += av.w * bv.w;
                }
            }
        }
        __syncthreads();
    }
    if (sact) {
#pragma unroll
        for (int r = 0; r < 4; r++)
#pragma unroll
            for (int cix = 0; cix < 4; cix++) {
                int v = v0 + r, w = w0 + cix;
                if (v < Vv && w < Vv) atomicAdd(&gsm[v * 25 + w], greg[r * 4 + cix]);
            }
    }
    __syncthreads();
    for (int j = tid; j < 625; j += 256) atomicAdd(&g_scores[ns * 625 + j], gsm[j]);
}

// ---------------- K2: softmax + adapt (padded 28) -----------------------------
__global__ void k_softmax(const float* __restrict__ A, const float* __restrict__ W) {
    int ns = blockIdx.x;
    int s = ns % Ss;
    int w = threadIdx.x;
    if (w >= 28) return;
    if (w >= Vv) {
#pragma unroll
        for (int v = 0; v < Vv; v++) g_adapt[ns * 700 + v * 28 + w] = 0.f;
        return;
    }
    float col[Vv];
    const float inv = 1.f / 4800.f;
    float m = -1e30f;
#pragma unroll
    for (int v = 0; v < Vv; v++) {
        col[v] = g_scores[ns * 625 + v * 25 + w] * inv;
        m = fmaxf(m, col[v]);
    }
    float sum = 0.f;
#pragma unroll
    for (int v = 0; v < Vv; v++) { col[v] = __expf(col[v] - m); sum += col[v]; }
    float r = 1.f / sum;
#pragma unroll
    for (int v = 0; v < Vv; v++) {
        int off = s * 625 + v * 25 + w;
        g_adapt[ns * 700 + v * 28 + w] = A[off] + W[off] + col[v] * r;
    }
}

// ---------------- K3: fused z + tf32 mma.sync, small tile, 3 blocks/SM --------
// grid (64, 60): (n, 5-t tile -> 125 cols). block 256 = 8 warps.
// Dynamic smem (floats):
//   xs  2 x 1000 @ 0       zt 2 x 3264 @ 2000 ([k][col pad 136])
//   wds 2 x 1664 @ 8528    ad3 2100 @ 11856   total 13956
//   ysm 64 x 132 @ 0 (epilogue alias)
#define FM_SMEM_FLOATS 13956
__global__ void __launch_bounds__(256, 3)
k_fused_mma(const float* __restrict__ x, const float* __restrict__ wd) {
    extern __shared__ float dsm[];
    float* ad3 = dsm + 11856;
    float* ysm = dsm;

    int n = blockIdx.x;
    int t0 = blockIdx.y * 5;           // 125 cols
    int tid = threadIdx.x;
    int wid = tid >> 5, lane = tid & 31;
    int gID = lane >> 2, tig = lane & 3;

    float d[8][4];
#pragma unroll
    for (int nt = 0; nt < 8; nt++)
#pragma unroll
        for (int e = 0; e < 4; e++) d[nt][e] = 0.f;

    // z mapping: 168 threads = (krow 0..23, q 0..6); each does all 5 tp
    int krow = tid / 7, zq = tid - krow * 7;
    bool zact = (tid < 168);
    int zs = krow >> 3, zc = krow & 7;

    int otile = wid & 3, nhalf = wid >> 2;
    int col0 = nhalf * 64;

    // ---- prologue ----
    for (int j = tid; j < 2100; j += 256) ad3[j] = g_adapt[n * 2100 + j];
    for (int j = tid; j < 1000; j += 256) {
        int cc = j / 125, j2 = j - cc * 125;
        dsm[cc * 125 + j2] = x[(size_t)(n * Cc + cc) * TV + t0 * 25 + j2];
    }
    for (int j = tid; j < 1536; j += 256) {
        int o = j / 24, kk = j - o * 24;
        int s = kk >> 3, cc = kk & 7;
        dsm[8528 + o * 26 + kk] = wd[(size_t)((s << 6) + o) * 64 + cc];
    }
    __syncthreads();

    for (int c = 0; c < 8; c++) {
        int buf = c & 1, nbuf = buf ^ 1;
        float* xsb = dsm + buf * 1000;
        float* xsn = dsm + nbuf * 1000;
        float* ztb = dsm + 2000 + buf * 3264;
        float* wdb = dsm + 8528 + buf * 1664;
        float* wdn = dsm + 8528 + nbuf * 1664;

        // ---- phase 1: prefetch next x; z-compute(c) ----
        if (c < 7) {
            int c0n = (c + 1) * 8;
            for (int j = tid; j < 1000; j += 256) {
                int cc = j / 125, j2 = j - cc * 125;
                xsn[cc * 125 + j2] = x[(size_t)(n * Cc + c0n + cc) * TV + t0 * 25 + j2];
            }
        }
        if (zact) {
            const float* adp = ad3 + zs * 700 + zq * 4;
            const float* xbase = xsb + zc * 125;
            float acc[5][4];
#pragma unroll
            for (int tp = 0; tp < 5; tp++)
#pragma unroll
                for (int e = 0; e < 4; e++) acc[tp][e] = 0.f;
#pragma unroll
            for (int vt = 0; vt < 5; vt++) {
                float4 ad[5];
#pragma unroll
                for (int u = 0; u < 5; u++)
                    ad[u] = *(const float4*)(adp + (vt * 5 + u) * 28);
#pragma unroll
                for (int tp = 0; tp < 5; tp++) {
                    const float* xr = xbase + tp * 25 + vt * 5;
                    float x0 = xr[0], x1 = xr[1], x2 = xr[2], x3 = xr[3], x4 = xr[4];
                    acc[tp][0] += x0 * ad[0].x; acc[tp][1] += x0 * ad[0].y;
                    acc[tp][2] += x0 * ad[0].z; acc[tp][3] += x0 * ad[0].w;
                    acc[tp][0] += x1 * ad[1].x; acc[tp][1] += x1 * ad[1].y;
                    acc[tp][2] += x1 * ad[1].z; acc[tp][3] += x1 * ad[1].w;
                    acc[tp][0] += x2 * ad[2].x; acc[tp][1] += x2 * ad[2].y;
                    acc[tp][2] += x2 * ad[2].z; acc[tp][3] += x2 * ad[2].w;
                    acc[tp][0] += x3 * ad[3].x; acc[tp][1] += x3 * ad[3].y;
                    acc[tp][2] += x3 * ad[3].z; acc[tp][3] += x3 * ad[3].w;
                    acc[tp][0] += x4 * ad[4].x; acc[tp][1] += x4 * ad[4].y;
                    acc[tp][2] += x4 * ad[4].z; acc[tp][3] += x4 * ad[4].w;
                }
            }
            float* zrow = ztb + krow * 136;
            int wbase = zq * 4;
#pragma unroll
            for (int tp = 0; tp < 5; tp++) {
#pragma unroll
                for (int e = 0; e < 4; e++) {
                    int w = wbase + e;
                    if (w < 25) zrow[tp * 25 + w] = acc[tp][e];
                }
            }
        }
        __syncthreads();   // the only barrier per chunk

        // ---- phase 2: prefetch next wd; mma(c) ----
        if (c < 7) {
            int c0n = (c + 1) * 8;
            for (int j = tid; j < 1536; j += 256) {
                int o = j / 24, kk = j - o * 24;
                int s = kk >> 3, cc = kk & 7;
                wdn[o * 26 + kk] = wd[(size_t)((s << 6) + o) * 64 + c0n + cc];
            }
        }
#pragma unroll
        for (int ks = 0; ks < 3; ks++) {
            int k0 = ks * 8;
            int arow = otile * 16 + gID;
            uint32_t a0 = __float_as_uint(wdb[arow * 26 + k0 + tig]);
            uint32_t a1 = __float_as_uint(wdb[(arow + 8) * 26 + k0 + tig]);
            uint32_t a2 = __float_as_uint(wdb[arow * 26 + k0 + 4 + tig]);
            uint32_t a3 = __float_as_uint(wdb[(arow + 8) * 26 + k0 + 4 + tig]);
#pragma unroll
            for (int nt = 0; nt < 8; nt++) {
                int nc = col0 + nt * 8 + gID;
                uint32_t b0 = __float_as_uint(ztb[(k0 + tig) * 136 + nc]);
                uint32_t b1 = __float_as_uint(ztb[(k0 + 4 + tig) * 136 + nc]);
                asm volatile(
                    "mma.sync.aligned.m16n8k8.row.col.f32.tf32.tf32.f32 "
                    "{%0,%1,%2,%3}, {%4,%5,%6,%7}, {%8,%9}, {%0,%1,%2,%3};"
                    : "+f"(d[nt][0]), "+f"(d[nt][1]), "+f"(d[nt][2]), "+f"(d[nt][3])
                    : "r"(a0), "r"(a1), "r"(a2), "r"(a3), "r"(b0), "r"(b1));
            }
        }
    }

    // ---- epilogue: stage D to ysm, coalesced store + BN stats ----
    __syncthreads();
#pragma unroll
    for (int nt = 0; nt < 8; nt++) {
        int colb = col0 + nt * 8 + tig * 2;
        int r0 = otile * 16 + gID;
        ysm[r0 * 132 + colb]           = d[nt][0];
        ysm[r0 * 132 + colb + 1]       = d[nt][1];
        ysm[(r0 + 8) * 132 + colb]     = d[nt][2];
        ysm[(r0 + 8) * 132 + colb + 1] = d[nt][3];
    }
    __syncthreads();
#pragma unroll 1
    for (int rr = 0; rr < 8; rr++) {
        int o = wid * 8 + rr;
        float bias = g_bdsum[o];
        float s1 = 0.f, s2 = 0.f;
        float* yp = g_y + (size_t)(n * Cc + o) * TV + t0 * 25;
        for (int col = lane; col < 125; col += 32) {
            float v = ysm[o * 132 + col] + bias;
            yp[col] = v;
            s1 += v; s2 += v * v;
        }
#pragma unroll
        for (int dd = 16; dd > 0; dd >>= 1) {
            s1 += __shfl_xor_sync(0xffffffffu, s1, dd);
            s2 += __shfl_xor_sync(0xffffffffu, s2, dd);
        }
        if (lane == 0) {
            atomicAdd(&g_stats[o], s1);
            atomicAdd(&g_stats[64 + o], s2);
        }
    }
}

// ---------------- K4: normalize + gamma/beta + residual + relu ----------------
__global__ void k_final(const float* __restrict__ x,
                        const float* __restrict__ gamma, const float* __restrict__ beta,
                        float* __restrict__ out) {
    int i4 = blockIdx.x * 256 + threadIdx.x;
    int c = (i4 / 1875) & 63;
    float s1 = g_stats[c], s2 = g_stats[64 + c];
    float mean = s1 / CNT_BN;
    float var = s2 / CNT_BN - mean * mean;
    float scale = gamma[c] * rsqrtf(var + EPS_BN);
    float bet = beta[c];
    float4 yv = ((const float4*)g_y)[i4];
    float4 xv = ((const float4*)x)[i4];
    float4 o;
    o.x = fmaxf(0.f, (yv.x - mean) * scale + bet + xv.x);
    o.y = fmaxf(0.f, (yv.y - mean) * scale + bet + xv.y);
    o.z = fmaxf(0.f, (yv.z - mean) * scale + bet + xv.z);
    o.w = fmaxf(0.f, (yv.w - mean) * scale + bet + xv.w);
    ((float4*)out)[i4] = o;
}

// ---------------- launch ------------------------------------------------------
extern "C" void kernel_launch(void* const* d_in, const int* in_sizes, int n_in,
                              void* d_out, int out_size) {
    const float* x     = (const float*)d_in[0];
    const float* A     = (const float*)d_in[1];
    const float* W     = (const float*)d_in[2];
    const float* wa    = (const float*)d_in[3];
    const float* ba    = (const float*)d_in[4];
    const float* wb    = (const float*)d_in[5];
    const float* bb    = (const float*)d_in[6];
    const float* wd    = (const float*)d_in[7];
    const float* bd    = (const float*)d_in[8];
    const float* gamma = (const float*)d_in[9];
    const float* beta  = (const float*)d_in[10];
    float* out = (float*)d_out;

    static bool attr_set = false;
    if (!attr_set) {
        cudaFuncSetAttribute(k_attn, cudaFuncAttributeMaxDynamicSharedMemorySize, 84 * 1024);
        cudaFuncSetAttribute(k_fused_mma, cudaFuncAttributeMaxDynamicSharedMemorySize,
                             FM_SMEM_FLOATS * sizeof(float));
        attr_set = true;
    }

    k_prep<<<472, 256>>>(wd, bd);
    k_attn<<<dim3(NS, 3), 256, 20625 * sizeof(float)>>>(x, wa, ba, wb, bb);
    k_softmax<<<NS, 32>>>(A, W);
    k_fused_mma<<<dim3(Nn, 60), 256, FM_SMEM_FLOATS * sizeof(float)>>>(x, wd);
    k_final<<<30000, 256>>>(x, gamma, beta, out);
}

// round 10
// speedup vs baseline: 1.3634x; 1.1663x over previous
#include <cuda_runtime.h>
#include <cstdint>

// Problem constants
#define Nn 64
#define Cc 64
#define Tt 300
#define Vv 25
#define Ss 3
#define TV 7500
#define NS 192
#define CNT_BN 480000.0f
#define EPS_BN 1e-5f

// ---------------- scratch -----------------------------------------------------
__device__ float g_scores[NS * 625];
__device__ float g_adapt[NS * 700];               // [ns][v][w pad 28]
__device__ float g_y[(size_t)Nn * Cc * TV];
__device__ float g_bdsum[Cc];
__device__ float g_stats[2 * Cc];

#define MMA_TF32(d, a0, a1, a2, a3, b0, b1)                                   \
    asm volatile(                                                              \
        "mma.sync.aligned.m16n8k8.row.col.f32.tf32.tf32.f32 "                  \
        "{%0,%1,%2,%3}, {%4,%5,%6,%7}, {%8,%9}, {%0,%1,%2,%3};"                \
        : "+f"((d)[0]), "+f"((d)[1]), "+f"((d)[2]), "+f"((d)[3])               \
        : "r"(a0), "r"(a1), "r"(a2), "r"(a3), "r"(b0), "r"(b1))

// ---------------- K0: prep ----------------------------------------------------
__global__ void k_prep(const float* __restrict__ wd, const float* __restrict__ bd) {
    int idx = blockIdx.x * 256 + threadIdx.x;
    if (idx < NS * 625) g_scores[idx] = 0.f;
    if (idx < Cc) g_bdsum[idx] = bd[idx] + bd[64 + idx] + bd[128 + idx];
    if (idx < 2 * Cc) g_stats[idx] = 0.f;
}

// ---------------- K1: tensor-core projection + scores -------------------------
// grid (192, 3): (ns, 100-t chunk = 2500 cols). block 256 = 8 warps.
// Per 125-col batch: proj D[32,128] = wabT[32,64] @ xs[64,128] (tf32 mma),
// store to ab [row][tp*32+v] (+bias, pads 0); then scores mma M32 N32 K80,
// accumulated in registers across all 20 batches.
// smem floats: wabT[32][68]@0 (2176) | bias@2176 (32) | xs 2x[64][136]@2208
//              (17408) | ab[32][168]@19616 (5376)  -> total 24992
#define KA_SMEM_FLOATS 24992
__global__ void __launch_bounds__(256, 2)
k_attn_mma(const float* __restrict__ x,
           const float* __restrict__ wa, const float* __restrict__ ba,
           const float* __restrict__ wb, const float* __restrict__ bb) {
    extern __shared__ float sm[];
    float* wabT = sm;             // [32][68]
    float* bias = sm + 2176;      // [32]
    float* xs   = sm + 2208;      // 2 x [64][136]
    float* ab   = sm + 19616;     // [32][168] = [row][tp*32 + v], v>=25 zero

    int ns = blockIdx.x;
    int n = ns / Ss, s = ns - n * Ss;
    int tid = threadIdx.x;
    int wid = tid >> 5, lane = tid & 31;
    int g = lane >> 2, tig = lane & 3;

    for (int j = tid; j < 2048; j += 256) {
        int row = j >> 6, k = j & 63;
        wabT[row * 68 + k] = (row < 16) ? wa[(s * 16 + row) * 64 + k]
                                        : wb[(s * 16 + row - 16) * 64 + k];
    }
    if (tid < 32) bias[tid] = (tid < 16) ? ba[s * 16 + tid] : bb[s * 16 + tid - 16];
    for (int j = tid; j < 5376; j += 256) ab[j] = 0.f;

    const float* xn = x + (size_t)n * Cc * TV;
    int colchunk = blockIdx.y * 2500;

    // prologue: batch 0 into buf 0
    for (int j = tid; j < 8192; j += 256) {
        int row = j >> 7, col = j & 127;
        xs[row * 136 + col] = (col < 125) ? xn[(size_t)row * TV + colchunk + col] : 0.f;
    }
    __syncthreads();

    float sc[4] = {0.f, 0.f, 0.f, 0.f};
    int smt = wid >> 2, snt = wid & 3;       // scores (mt, nt) per warp

    for (int b = 0; b < 20; b++) {
        int buf = b & 1;
        float* xb  = xs + buf * 8704;
        float* xnb = xs + (buf ^ 1) * 8704;

        // ---- phase 1: prefetch next batch; proj mma ----
        if (b < 19) {
            int cb = colchunk + (b + 1) * 125;
            for (int j = tid; j < 8192; j += 256) {
                int row = j >> 7, col = j & 127;
                xnb[row * 136 + col] = (col < 125) ? xn[(size_t)row * TV + cb + col] : 0.f;
            }
        }
        float dd[2][2][4];
#pragma unroll
        for (int mt = 0; mt < 2; mt++)
#pragma unroll
            for (int lnt = 0; lnt < 2; lnt++)
#pragma unroll
                for (int e = 0; e < 4; e++) dd[mt][lnt][e] = 0.f;
#pragma unroll
        for (int ks = 0; ks < 8; ks++) {
            int k0 = ks * 8;
            uint32_t af[2][4];
#pragma unroll
            for (int mt = 0; mt < 2; mt++) {
                int r = mt * 16 + g;
                af[mt][0] = __float_as_uint(wabT[r * 68 + k0 + tig]);
                af[mt][1] = __float_as_uint(wabT[(r + 8) * 68 + k0 + tig]);
                af[mt][2] = __float_as_uint(wabT[r * 68 + k0 + 4 + tig]);
                af[mt][3] = __float_as_uint(wabT[(r + 8) * 68 + k0 + 4 + tig]);
            }
#pragma unroll
            for (int lnt = 0; lnt < 2; lnt++) {
                int col = (wid * 2 + lnt) * 8 + g;
                uint32_t b0 = __float_as_uint(xb[(k0 + tig) * 136 + col]);
                uint32_t b1 = __float_as_uint(xb[(k0 + 4 + tig) * 136 + col]);
#pragma unroll
                for (int mt = 0; mt < 2; mt++)
                    MMA_TF32(dd[mt][lnt], af[mt][0], af[mt][1], af[mt][2], af[mt][3], b0, b1);
            }
        }
        // store proj -> ab with bias (cols >=125 dropped; v pads stay 0)
#pragma unroll
        for (int mt = 0; mt < 2; mt++)
#pragma unroll
            for (int lnt = 0; lnt < 2; lnt++)
#pragma unroll
                for (int e = 0; e < 4; e++) {
                    int r = mt * 16 + g + ((e >> 1) << 3);     // +8 for e=2,3
                    int cg = (wid * 2 + lnt) * 8 + tig * 2 + (e & 1);
                    if (cg < 125) {
                        int tp = cg / 25, v = cg - tp * 25;
                        ab[r * 168 + tp * 32 + v] = dd[mt][lnt][e] + bias[r];
                    }
                }
        __syncthreads();   // ab ready

        // ---- phase 2: scores mma (K=80) ----
#pragma unroll
        for (int ks = 0; ks < 10; ks++) {
            int ka = ks * 8 + tig, kb = ka + 4;
            int ia = ka / 5, tpa = ka - ia * 5;
            int ib = kb / 5, tpb = kb - ib * 5;
            int va = smt * 16 + g;
            uint32_t a0 = __float_as_uint(ab[ia * 168 + tpa * 32 + va]);
            uint32_t a1 = __float_as_uint(ab[ia * 168 + tpa * 32 + va + 8]);
            uint32_t a2 = __float_as_uint(ab[ib * 168 + tpb * 32 + va]);
            uint32_t a3 = __float_as_uint(ab[ib * 168 + tpb * 32 + va + 8]);
            int wcol = snt * 8 + g;
            uint32_t b0 = __float_as_uint(ab[(16 + ia) * 168 + tpa * 32 + wcol]);
            uint32_t b1 = __float_as_uint(ab[(16 + ib) * 168 + tpb * 32 + wcol]);
            MMA_TF32(sc, a0, a1, a2, a3, b0, b1);
        }
        __syncthreads();   // scores read done before next ab overwrite
    }

    // writeout: thread owns rows {v, v+8} x cols {w, w+1}
    {
        int v = smt * 16 + g;
        int w = snt * 8 + tig * 2;
        float* gs = g_scores + ns * 625;
        if (v < 25) {
            if (w < 25)     atomicAdd(&gs[v * 25 + w], sc[0]);
            if (w + 1 < 25) atomicAdd(&gs[v * 25 + w + 1], sc[1]);
        }
        if (v + 8 < 25) {
            if (w < 25)     atomicAdd(&gs[(v + 8) * 25 + w], sc[2]);
            if (w + 1 < 25) atomicAdd(&gs[(v + 8) * 25 + w + 1], sc[3]);
        }
    }
}

// ---------------- K2: softmax + adapt (padded 28) -----------------------------
__global__ void k_softmax(const float* __restrict__ A, const float* __restrict__ W) {
    int ns = blockIdx.x;
    int s = ns % Ss;
    int w = threadIdx.x;
    if (w >= 28) return;
    if (w >= Vv) {
#pragma unroll
        for (int v = 0; v < Vv; v++) g_adapt[ns * 700 + v * 28 + w] = 0.f;
        return;
    }
    float col[Vv];
    const float inv = 1.f / 4800.f;
    float m = -1e30f;
#pragma unroll
    for (int v = 0; v < Vv; v++) {
        col[v] = g_scores[ns * 625 + v * 25 + w] * inv;
        m = fmaxf(m, col[v]);
    }
    float sum = 0.f;
#pragma unroll
    for (int v = 0; v < Vv; v++) { col[v] = __expf(col[v] - m); sum += col[v]; }
    float r = 1.f / sum;
#pragma unroll
    for (int v = 0; v < Vv; v++) {
        int off = s * 625 + v * 25 + w;
        g_adapt[ns * 700 + v * 28 + w] = A[off] + W[off] + col[v] * r;
    }
}

// ---------------- K3: fused z + tf32 mma.sync (unchanged R9) ------------------
#define FM_SMEM_FLOATS 13956
__global__ void __launch_bounds__(256, 3)
k_fused_mma(const float* __restrict__ x, const float* __restrict__ wd) {
    extern __shared__ float dsm[];
    float* ad3 = dsm + 11856;
    float* ysm = dsm;

    int n = blockIdx.x;
    int t0 = blockIdx.y * 5;
    int tid = threadIdx.x;
    int wid = tid >> 5, lane = tid & 31;
    int gID = lane >> 2, tig = lane & 3;

    float d[8][4];
#pragma unroll
    for (int nt = 0; nt < 8; nt++)
#pragma unroll
        for (int e = 0; e < 4; e++) d[nt][e] = 0.f;

    int krow = tid / 7, zq = tid - krow * 7;
    bool zact = (tid < 168);
    int zs = krow >> 3, zc = krow & 7;

    int otile = wid & 3, nhalf = wid >> 2;
    int col0 = nhalf * 64;

    for (int j = tid; j < 2100; j += 256) ad3[j] = g_adapt[n * 2100 + j];
    for (int j = tid; j < 1000; j += 256) {
        int cc = j / 125, j2 = j - cc * 125;
        dsm[cc * 125 + j2] = x[(size_t)(n * Cc + cc) * TV + t0 * 25 + j2];
    }
    for (int j = tid; j < 1536; j += 256) {
        int o = j / 24, kk = j - o * 24;
        int s = kk >> 3, cc = kk & 7;
        dsm[8528 + o * 26 + kk] = wd[(size_t)((s << 6) + o) * 64 + cc];
    }
    __syncthreads();

    for (int c = 0; c < 8; c++) {
        int buf = c & 1, nbuf = buf ^ 1;
        float* xsb = dsm + buf * 1000;
        float* xsn = dsm + nbuf * 1000;
        float* ztb = dsm + 2000 + buf * 3264;
        float* wdb = dsm + 8528 + buf * 1664;
        float* wdn = dsm + 8528 + nbuf * 1664;

        if (c < 7) {
            int c0n = (c + 1) * 8;
            for (int j = tid; j < 1000; j += 256) {
                int cc = j / 125, j2 = j - cc * 125;
                xsn[cc * 125 + j2] = x[(size_t)(n * Cc + c0n + cc) * TV + t0 * 25 + j2];
            }
        }
        if (zact) {
            const float* adp = ad3 + zs * 700 + zq * 4;
            const float* xbase = xsb + zc * 125;
            float acc[5][4];
#pragma unroll
            for (int tp = 0; tp < 5; tp++)
#pragma unroll
                for (int e = 0; e < 4; e++) acc[tp][e] = 0.f;
#pragma unroll
            for (int vt = 0; vt < 5; vt++) {
                float4 ad[5];
#pragma unroll
                for (int u = 0; u < 5; u++)
                    ad[u] = *(const float4*)(adp + (vt * 5 + u) * 28);
#pragma unroll
                for (int tp = 0; tp < 5; tp++) {
                    const float* xr = xbase + tp * 25 + vt * 5;
                    float x0 = xr[0], x1 = xr[1], x2 = xr[2], x3 = xr[3], x4 = xr[4];
                    acc[tp][0] += x0 * ad[0].x; acc[tp][1] += x0 * ad[0].y;
                    acc[tp][2] += x0 * ad[0].z; acc[tp][3] += x0 * ad[0].w;
                    acc[tp][0] += x1 * ad[1].x; acc[tp][1] += x1 * ad[1].y;
                    acc[tp][2] += x1 * ad[1].z; acc[tp][3] += x1 * ad[1].w;
                    acc[tp][0] += x2 * ad[2].x; acc[tp][1] += x2 * ad[2].y;
                    acc[tp][2] += x2 * ad[2].z; acc[tp][3] += x2 * ad[2].w;
                    acc[tp][0] += x3 * ad[3].x; acc[tp][1] += x3 * ad[3].y;
                    acc[tp][2] += x3 * ad[3].z; acc[tp][3] += x3 * ad[3].w;
                    acc[tp][0] += x4 * ad[4].x; acc[tp][1] += x4 * ad[4].y;
                    acc[tp][2] += x4 * ad[4].z; acc[tp][3] += x4 * ad[4].w;
                }
            }
            float* zrow = ztb + krow * 136;
            int wbase = zq * 4;
#pragma unroll
            for (int tp = 0; tp < 5; tp++) {
#pragma unroll
                for (int e = 0; e < 4; e++) {
                    int w = wbase + e;
                    if (w < 25) zrow[tp * 25 + w] = acc[tp][e];
                }
            }
        }
        __syncthreads();

        if (c < 7) {
            int c0n = (c + 1) * 8;
            for (int j = tid; j < 1536; j += 256) {
                int o = j / 24, kk = j - o * 24;
                int s = kk >> 3, cc = kk & 7;
                wdn[o * 26 + kk] = wd[(size_t)((s << 6) + o) * 64 + c0n + cc];
            }
        }
#pragma unroll
        for (int ks = 0; ks < 3; ks++) {
            int k0 = ks * 8;
            int arow = otile * 16 + gID;
            uint32_t a0 = __float_as_uint(wdb[arow * 26 + k0 + tig]);
            uint32_t a1 = __float_as_uint(wdb[(arow + 8) * 26 + k0 + tig]);
            uint32_t a2 = __float_as_uint(wdb[arow * 26 + k0 + 4 + tig]);
            uint32_t a3 = __float_as_uint(wdb[(arow + 8) * 26 + k0 + 4 + tig]);
#pragma unroll
            for (int nt = 0; nt < 8; nt++) {
                int nc = col0 + nt * 8 + gID;
                uint32_t b0 = __float_as_uint(ztb[(k0 + tig) * 136 + nc]);
                uint32_t b1 = __float_as_uint(ztb[(k0 + 4 + tig) * 136 + nc]);
                MMA_TF32(d[nt], a0, a1, a2, a3, b0, b1);
            }
        }
    }

    __syncthreads();
#pragma unroll
    for (int nt = 0; nt < 8; nt++) {
        int colb = col0 + nt * 8 + tig * 2;
        int r0 = otile * 16 + gID;
        ysm[r0 * 132 + colb]           = d[nt][0];
        ysm[r0 * 132 + colb + 1]       = d[nt][1];
        ysm[(r0 + 8) * 132 + colb]     = d[nt][2];
        ysm[(r0 + 8) * 132 + colb + 1] = d[nt][3];
    }
    __syncthreads();
#pragma unroll 1
    for (int rr = 0; rr < 8; rr++) {
        int o = wid * 8 + rr;
        float bias = g_bdsum[o];
        float s1 = 0.f, s2 = 0.f;
        float* yp = g_y + (size_t)(n * Cc + o) * TV + t0 * 25;
        for (int col = lane; col < 125; col += 32) {
            float v = ysm[o * 132 + col] + bias;
            yp[col] = v;
            s1 += v; s2 += v * v;
        }
#pragma unroll
        for (int dd2 = 16; dd2 > 0; dd2 >>= 1) {
            s1 += __shfl_xor_sync(0xffffffffu, s1, dd2);
            s2 += __shfl_xor_sync(0xffffffffu, s2, dd2);
        }
        if (lane == 0) {
            atomicAdd(&g_stats[o], s1);
            atomicAdd(&g_stats[64 + o], s2);
        }
    }
}

// ---------------- K4: normalize + gamma/beta + residual + relu ----------------
__global__ void k_final(const float* __restrict__ x,
                        const float* __restrict__ gamma, const float* __restrict__ beta,
                        float* __restrict__ out) {
    int i4 = blockIdx.x * 256 + threadIdx.x;
    int c = (i4 / 1875) & 63;
    float s1 = g_stats[c], s2 = g_stats[64 + c];
    float mean = s1 / CNT_BN;
    float var = s2 / CNT_BN - mean * mean;
    float scale = gamma[c] * rsqrtf(var + EPS_BN);
    float bet = beta[c];
    float4 yv = ((const float4*)g_y)[i4];
    float4 xv = ((const float4*)x)[i4];
    float4 o;
    o.x = fmaxf(0.f, (yv.x - mean) * scale + bet + xv.x);
    o.y = fmaxf(0.f, (yv.y - mean) * scale + bet + xv.y);
    o.z = fmaxf(0.f, (yv.z - mean) * scale + bet + xv.z);
    o.w = fmaxf(0.f, (yv.w - mean) * scale + bet + xv.w);
    ((float4*)out)[i4] = o;
}

// ---------------- launch ------------------------------------------------------
extern "C" void kernel_launch(void* const* d_in, const int* in_sizes, int n_in,
                              void* d_out, int out_size) {
    const float* x     = (const float*)d_in[0];
    const float* A     = (const float*)d_in[1];
    const float* W     = (const float*)d_in[2];
    const float* wa    = (const float*)d_in[3];
    const float* ba    = (const float*)d_in[4];
    const float* wb    = (const float*)d_in[5];
    const float* bb    = (const float*)d_in[6];
    const float* wd    = (const float*)d_in[7];
    const float* bd    = (const float*)d_in[8];
    const float* gamma = (const float*)d_in[9];
    const float* beta  = (const float*)d_in[10];
    float* out = (float*)d_out;

    static bool attr_set = false;
    if (!attr_set) {
        cudaFuncSetAttribute(k_attn_mma, cudaFuncAttributeMaxDynamicSharedMemorySize,
                             KA_SMEM_FLOATS * sizeof(float));
        cudaFuncSetAttribute(k_fused_mma, cudaFuncAttributeMaxDynamicSharedMemorySize,
                             FM_SMEM_FLOATS * sizeof(float));
        attr_set = true;
    }

    k_prep<<<472, 256>>>(wd, bd);
    k_attn_mma<<<dim3(NS, 3), 256, KA_SMEM_FLOATS * sizeof(float)>>>(x, wa, ba, wb, bb);
    k_softmax<<<NS, 32>>>(A, W);
    k_fused_mma<<<dim3(Nn, 60), 256, FM_SMEM_FLOATS * sizeof(float)>>>(x, wd);
    k_final<<<30000, 256>>>(x, gamma, beta, out);
}

// round 11
// speedup vs baseline: 1.4351x; 1.0526x over previous
#include <cuda_runtime.h>
#include <cstdint>

// Problem constants
#define Nn 64
#define Cc 64
#define Tt 300
#define Vv 25
#define Ss 3
#define TV 7500
#define NS 192
#define CNT_BN 480000.0f
#define EPS_BN 1e-5f

// ---------------- scratch -----------------------------------------------------
__device__ float g_scores[NS * 625];
__device__ float g_adapt[NS * 700];               // [ns][v][w pad 28]
__device__ float g_y[(size_t)Nn * Cc * TV];
__device__ float g_bdsum[Cc];
__device__ float g_stats[2 * Cc];

#define MMA_TF32(d, a0, a1, a2, a3, b0, b1)                                   \
    asm volatile(                                                              \
        "mma.sync.aligned.m16n8k8.row.col.f32.tf32.tf32.f32 "                  \
        "{%0,%1,%2,%3}, {%4,%5,%6,%7}, {%8,%9}, {%0,%1,%2,%3};"                \
        : "+f"((d)[0]), "+f"((d)[1]), "+f"((d)[2]), "+f"((d)[3])               \
        : "r"(a0), "r"(a1), "r"(a2), "r"(a3), "r"(b0), "r"(b1))

// ---------------- K0: prep ----------------------------------------------------
__global__ void k_prep(const float* __restrict__ wd, const float* __restrict__ bd) {
    int idx = blockIdx.x * 256 + threadIdx.x;
    if (idx < NS * 625) g_scores[idx] = 0.f;
    if (idx < Cc) g_bdsum[idx] = bd[idx] + bd[64 + idx] + bd[128 + idx];
    if (idx < 2 * Cc) g_stats[idx] = 0.f;
}

// ---------------- K1: tensor-core projection + scores (unchanged R10) ---------
#define KA_SMEM_FLOATS 24992
__global__ void __launch_bounds__(256, 2)
k_attn_mma(const float* __restrict__ x,
           const float* __restrict__ wa, const float* __restrict__ ba,
           const float* __restrict__ wb, const float* __restrict__ bb) {
    extern __shared__ float sm[];
    float* wabT = sm;             // [32][68]
    float* bias = sm + 2176;      // [32]
    float* xs   = sm + 2208;      // 2 x [64][136]
    float* ab   = sm + 19616;     // [32][168]

    int ns = blockIdx.x;
    int n = ns / Ss, s = ns - n * Ss;
    int tid = threadIdx.x;
    int wid = tid >> 5, lane = tid & 31;
    int g = lane >> 2, tig = lane & 3;

    for (int j = tid; j < 2048; j += 256) {
        int row = j >> 6, k = j & 63;
        wabT[row * 68 + k] = (row < 16) ? wa[(s * 16 + row) * 64 + k]
                                        : wb[(s * 16 + row - 16) * 64 + k];
    }
    if (tid < 32) bias[tid] = (tid < 16) ? ba[s * 16 + tid] : bb[s * 16 + tid - 16];
    for (int j = tid; j < 5376; j += 256) ab[j] = 0.f;

    const float* xn = x + (size_t)n * Cc * TV;
    int colchunk = blockIdx.y * 2500;

    for (int j = tid; j < 8192; j += 256) {
        int row = j >> 7, col = j & 127;
        xs[row * 136 + col] = (col < 125) ? xn[(size_t)row * TV + colchunk + col] : 0.f;
    }
    __syncthreads();

    float sc[4] = {0.f, 0.f, 0.f, 0.f};
    int smt = wid >> 2, snt = wid & 3;

    for (int b = 0; b < 20; b++) {
        int buf = b & 1;
        float* xb  = xs + buf * 8704;
        float* xnb = xs + (buf ^ 1) * 8704;

        if (b < 19) {
            int cb = colchunk + (b + 1) * 125;
            for (int j = tid; j < 8192; j += 256) {
                int row = j >> 7, col = j & 127;
                xnb[row * 136 + col] = (col < 125) ? xn[(size_t)row * TV + cb + col] : 0.f;
            }
        }
        float dd[2][2][4];
#pragma unroll
        for (int mt = 0; mt < 2; mt++)
#pragma unroll
            for (int lnt = 0; lnt < 2; lnt++)
#pragma unroll
                for (int e = 0; e < 4; e++) dd[mt][lnt][e] = 0.f;
#pragma unroll
        for (int ks = 0; ks < 8; ks++) {
            int k0 = ks * 8;
            uint32_t af[2][4];
#pragma unroll
            for (int mt = 0; mt < 2; mt++) {
                int r = mt * 16 + g;
                af[mt][0] = __float_as_uint(wabT[r * 68 + k0 + tig]);
                af[mt][1] = __float_as_uint(wabT[(r + 8) * 68 + k0 + tig]);
                af[mt][2] = __float_as_uint(wabT[r * 68 + k0 + 4 + tig]);
                af[mt][3] = __float_as_uint(wabT[(r + 8) * 68 + k0 + 4 + tig]);
            }
#pragma unroll
            for (int lnt = 0; lnt < 2; lnt++) {
                int col = (wid * 2 + lnt) * 8 + g;
                uint32_t b0 = __float_as_uint(xb[(k0 + tig) * 136 + col]);
                uint32_t b1 = __float_as_uint(xb[(k0 + 4 + tig) * 136 + col]);
#pragma unroll
                for (int mt = 0; mt < 2; mt++)
                    MMA_TF32(dd[mt][lnt], af[mt][0], af[mt][1], af[mt][2], af[mt][3], b0, b1);
            }
        }
#pragma unroll
        for (int mt = 0; mt < 2; mt++)
#pragma unroll
            for (int lnt = 0; lnt < 2; lnt++)
#pragma unroll
                for (int e = 0; e < 4; e++) {
                    int r = mt * 16 + g + ((e >> 1) << 3);
                    int cg = (wid * 2 + lnt) * 8 + tig * 2 + (e & 1);
                    if (cg < 125) {
                        int tp = cg / 25, v = cg - tp * 25;
                        ab[r * 168 + tp * 32 + v] = dd[mt][lnt][e] + bias[r];
                    }
                }
        __syncthreads();

#pragma unroll
        for (int ks = 0; ks < 10; ks++) {
            int ka = ks * 8 + tig, kb = ka + 4;
            int ia = ka / 5, tpa = ka - ia * 5;
            int ib = kb / 5, tpb = kb - ib * 5;
            int va = smt * 16 + g;
            uint32_t a0 = __float_as_uint(ab[ia * 168 + tpa * 32 + va]);
            uint32_t a1 = __float_as_uint(ab[ia * 168 + tpa * 32 + va + 8]);
            uint32_t a2 = __float_as_uint(ab[ib * 168 + tpb * 32 + va]);
            uint32_t a3 = __float_as_uint(ab[ib * 168 + tpb * 32 + va + 8]);
            int wcol = snt * 8 + g;
            uint32_t b0 = __float_as_uint(ab[(16 + ia) * 168 + tpa * 32 + wcol]);
            uint32_t b1 = __float_as_uint(ab[(16 + ib) * 168 + tpb * 32 + wcol]);
            MMA_TF32(sc, a0, a1, a2, a3, b0, b1);
        }
        __syncthreads();
    }

    {
        int v = smt * 16 + g;
        int w = snt * 8 + tig * 2;
        float* gs = g_scores + ns * 625;
        if (v < 25) {
            if (w < 25)     atomicAdd(&gs[v * 25 + w], sc[0]);
            if (w + 1 < 25) atomicAdd(&gs[v * 25 + w + 1], sc[1]);
        }
        if (v + 8 < 25) {
            if (w < 25)     atomicAdd(&gs[(v + 8) * 25 + w], sc[2]);
            if (w + 1 < 25) atomicAdd(&gs[(v + 8) * 25 + w + 1], sc[3]);
        }
    }
}

// ---------------- K2: softmax + adapt (padded 28) -----------------------------
__global__ void k_softmax(const float* __restrict__ A, const float* __restrict__ W) {
    int ns = blockIdx.x;
    int s = ns % Ss;
    int w = threadIdx.x;
    if (w >= 28) return;
    if (w >= Vv) {
#pragma unroll
        for (int v = 0; v < Vv; v++) g_adapt[ns * 700 + v * 28 + w] = 0.f;
        return;
    }
    float col[Vv];
    const float inv = 1.f / 4800.f;
    float m = -1e30f;
#pragma unroll
    for (int v = 0; v < Vv; v++) {
        col[v] = g_scores[ns * 625 + v * 25 + w] * inv;
        m = fmaxf(m, col[v]);
    }
    float sum = 0.f;
#pragma unroll
    for (int v = 0; v < Vv; v++) { col[v] = __expf(col[v] - m); sum += col[v]; }
    float r = 1.f / sum;
#pragma unroll
    for (int v = 0; v < Vv; v++) {
        int off = s * 625 + v * 25 + w;
        g_adapt[ns * 700 + v * 28 + w] = A[off] + W[off] + col[v] * r;
    }
}

// ---------------- K3: all-tensor fused kernel ---------------------------------
// grid (64, 60): (n, 5-t tile -> 125 cols). block 256 = 8 warps.
// Per chunk: warps 0-5 z-MMA (D[40,25] = X @ adaptT per s), warps 6-7 stage
// next x; 1 barrier; then all warps main GEMM MMA + wd prefetch.
// smem (floats): xs 2x1440 @0 ([cc][tp][36] pad) | zt 2x3264 @2880 ([k][136])
//   | wds 2x1664 @9408 | adT 3456 @12736 ([s][w][36]) -> 16192. ysm alias @0.
#define FM_SMEM_FLOATS 16192
#define XS0 0
#define ZT0 2880
#define WD0 9408
#define AD0 12736
__global__ void __launch_bounds__(256, 3)
k_fused_mma(const float* __restrict__ x, const float* __restrict__ wd) {
    extern __shared__ float dsm[];
    float* ysm = dsm;

    int n = blockIdx.x;
    int t0 = blockIdx.y * 5;
    int tid = threadIdx.x;
    int wid = tid >> 5, lane = tid & 31;
    int g = lane >> 2, tig = lane & 3;

    float d[8][4];
#pragma unroll
    for (int nt = 0; nt < 8; nt++)
#pragma unroll
        for (int e = 0; e < 4; e++) d[nt][e] = 0.f;

    int otile = wid & 3, nhalf = wid >> 2;
    int col0 = nhalf * 64;
    // z-mma assignment (warps 0..5): s = wid>>1, mgroup = wid&1
    int zsS = wid >> 1, mgroup = wid & 1;
    bool zwarp = (wid < 6);
    bool xwarp = (wid >= 6);

    // ---- prologue ----
    // adT[s][w][36] = adapt[s][v][w] transposed, pads 0 (single pass)
    for (int j = tid; j < 3456; j += 256) {
        int s = j / 1152, r = j - s * 1152;
        int w = r / 36, v = r - w * 36;
        dsm[AD0 + j] = (v < 25 && w < 25) ? g_adapt[n * 2100 + s * 700 + v * 28 + w] : 0.f;
    }
    // xs buf0 = chunk0 data (pads 0); buf1 = all 0 (pads stay 0 forever)
    for (int j = tid; j < 2880; j += 256) {
        float val = 0.f;
        if (j < 1440) {
            int cc = j / 180, r = j - cc * 180;
            int tp = r / 36, v = r - tp * 36;
            if (v < 25) val = x[(size_t)(n * Cc + cc) * TV + (t0 + tp) * 25 + v];
        }
        dsm[XS0 + j] = val;
    }
    for (int j = tid; j < 1536; j += 256) {
        int o = j / 24, kk = j - o * 24;
        int s = kk >> 3, cc = kk & 7;
        dsm[WD0 + o * 26 + kk] = wd[(size_t)((s << 6) + o) * 64 + cc];
    }
    __syncthreads();

    for (int c = 0; c < 8; c++) {
        int buf = c & 1, nbuf = buf ^ 1;
        float* xsb = dsm + XS0 + buf * 1440;
        float* xsn = dsm + XS0 + nbuf * 1440;
        float* ztb = dsm + ZT0 + buf * 3264;
        float* wdb = dsm + WD0 + buf * 1664;
        float* wdn = dsm + WD0 + nbuf * 1664;
        const float* adTs = dsm + AD0 + zsS * 1152;

        // ---- phase 1 ----
        if (xwarp) {
            if (c < 7) {
                int c0n = (c + 1) * 8;
                for (int j = tid - 192; j < 1000; j += 64) {
                    int cc = j / 125, r = j - cc * 125;
                    int tp = r / 25, v = r - tp * 25;
                    xsn[cc * 180 + tp * 36 + v] =
                        x[(size_t)(n * Cc + c0n + cc) * TV + (t0 + tp) * 25 + v];
                }
            }
        } else {
            // z-MMA: D[m=(cc,tp)][w] = sum_v xs[cc][tp][v] * adT[s][w][v]
            int nmt = mgroup ? 1 : 2;
#pragma unroll 2
            for (int mi = 0; mi < nmt; mi++) {
                int mt = mgroup ? 2 : mi;
                float dz[4][4];
#pragma unroll
                for (int nt = 0; nt < 4; nt++)
#pragma unroll
                    for (int e = 0; e < 4; e++) dz[nt][e] = 0.f;
#pragma unroll
                for (int ks = 0; ks < 4; ks++) {
                    int k0 = ks * 8;
                    int m0 = mt * 16 + g, m1 = m0 + 8;
                    uint32_t a0, a1, a2, a3;
                    {
                        int cc = m0 / 5, tp = m0 - cc * 5;
                        a0 = __float_as_uint(xsb[cc * 180 + tp * 36 + k0 + tig]);
                        a2 = __float_as_uint(xsb[cc * 180 + tp * 36 + k0 + 4 + tig]);
                    }
                    if (m1 < 40) {
                        int cc = m1 / 5, tp = m1 - cc * 5;
                        a1 = __float_as_uint(xsb[cc * 180 + tp * 36 + k0 + tig]);
                        a3 = __float_as_uint(xsb[cc * 180 + tp * 36 + k0 + 4 + tig]);
                    } else { a1 = 0u; a3 = 0u; }
#pragma unroll
                    for (int nt = 0; nt < 4; nt++) {
                        uint32_t b0 = __float_as_uint(adTs[(nt * 8 + g) * 36 + k0 + tig]);
                        uint32_t b1 = __float_as_uint(adTs[(nt * 8 + g) * 36 + k0 + 4 + tig]);
                        MMA_TF32(dz[nt], a0, a1, a2, a3, b0, b1);
                    }
                }
                // store valid D -> zt[k=s*8+cc][tp*25+w]
#pragma unroll
                for (int nt = 0; nt < 4; nt++)
#pragma unroll
                    for (int e = 0; e < 4; e++) {
                        int w = nt * 8 + tig * 2 + (e & 1);
                        int r = mt * 16 + g + ((e >> 1) << 3);
                        if (w < 25 && r < 40) {
                            int cc = r / 5, tp = r - cc * 5;
                            ztb[(zsS * 8 + cc) * 136 + tp * 25 + w] = dz[nt][e];
                        }
                    }
            }
        }
        __syncthreads();   // zt + xs[nbuf] ready

        // ---- phase 2: wd prefetch + main GEMM mma ----
        if (c < 7) {
            int c0n = (c + 1) * 8;
            for (int j = tid; j < 1536; j += 256) {
                int o = j / 24, kk = j - o * 24;
                int s = kk >> 3, cc = kk & 7;
                wdn[o * 26 + kk] = wd[(size_t)((s << 6) + o) * 64 + c0n + cc];
            }
        }
#pragma unroll
        for (int ks = 0; ks < 3; ks++) {
            int k0 = ks * 8;
            int arow = otile * 16 + g;
            uint32_t a0 = __float_as_uint(wdb[arow * 26 + k0 + tig]);
            uint32_t a1 = __float_as_uint(wdb[(arow + 8) * 26 + k0 + tig]);
            uint32_t a2 = __float_as_uint(wdb[arow * 26 + k0 + 4 + tig]);
            uint32_t a3 = __float_as_uint(wdb[(arow + 8) * 26 + k0 + 4 + tig]);
#pragma unroll
            for (int nt = 0; nt < 8; nt++) {
                int nc = col0 + nt * 8 + g;
                uint32_t b0 = __float_as_uint(ztb[(k0 + tig) * 136 + nc]);
                uint32_t b1 = __float_as_uint(ztb[(k0 + 4 + tig) * 136 + nc]);
                MMA_TF32(d[nt], a0, a1, a2, a3, b0, b1);
            }
        }
    }

    // ---- epilogue ----
    __syncthreads();
#pragma unroll
    for (int nt = 0; nt < 8; nt++) {
        int colb = col0 + nt * 8 + tig * 2;
        int r0 = otile * 16 + g;
        ysm[r0 * 132 + colb]           = d[nt][0];
        ysm[r0 * 132 + colb + 1]       = d[nt][1];
        ysm[(r0 + 8) * 132 + colb]     = d[nt][2];
        ysm[(r0 + 8) * 132 + colb + 1] = d[nt][3];
    }
    __syncthreads();
#pragma unroll 1
    for (int rr = 0; rr < 8; rr++) {
        int o = wid * 8 + rr;
        float bias = g_bdsum[o];
        float s1 = 0.f, s2 = 0.f;
        float* yp = g_y + (size_t)(n * Cc + o) * TV + t0 * 25;
        for (int col = lane; col < 125; col += 32) {
            float v = ysm[o * 132 + col] + bias;
            yp[col] = v;
            s1 += v; s2 += v * v;
        }
#pragma unroll
        for (int dd2 = 16; dd2 > 0; dd2 >>= 1) {
            s1 += __shfl_xor_sync(0xffffffffu, s1, dd2);
            s2 += __shfl_xor_sync(0xffffffffu, s2, dd2);
        }
        if (lane == 0) {
            atomicAdd(&g_stats[o], s1);
            atomicAdd(&g_stats[64 + o], s2);
        }
    }
}

// ---------------- K4: normalize + gamma/beta + residual + relu ----------------
__global__ void k_final(const float* __restrict__ x,
                        const float* __restrict__ gamma, const float* __restrict__ beta,
                        float* __restrict__ out) {
    int i4 = blockIdx.x * 256 + threadIdx.x;
    int c = (i4 / 1875) & 63;
    float s1 = g_stats[c], s2 = g_stats[64 + c];
    float mean = s1 / CNT_BN;
    float var = s2 / CNT_BN - mean * mean;
    float scale = gamma[c] * rsqrtf(var + EPS_BN);
    float bet = beta[c];
    float4 yv = ((const float4*)g_y)[i4];
    float4 xv = ((const float4*)x)[i4];
    float4 o;
    o.x = fmaxf(0.f, (yv.x - mean) * scale + bet + xv.x);
    o.y = fmaxf(0.f, (yv.y - mean) * scale + bet + xv.y);
    o.z = fmaxf(0.f, (yv.z - mean) * scale + bet + xv.z);
    o.w = fmaxf(0.f, (yv.w - mean) * scale + bet + xv.w);
    ((float4*)out)[i4] = o;
}

// ---------------- launch ------------------------------------------------------
extern "C" void kernel_launch(void* const* d_in, const int* in_sizes, int n_in,
                              void* d_out, int out_size) {
    const float* x     = (const float*)d_in[0];
    const float* A     = (const float*)d_in[1];
    const float* W     = (const float*)d_in[2];
    const float* wa    = (const float*)d_in[3];
    const float* ba    = (const float*)d_in[4];
    const float* wb    = (const float*)d_in[5];
    const float* bb    = (const float*)d_in[6];
    const float* wd    = (const float*)d_in[7];
    const float* bd    = (const float*)d_in[8];
    const float* gamma = (const float*)d_in[9];
    const float* beta  = (const float*)d_in[10];
    float* out = (float*)d_out;

    static bool attr_set = false;
    if (!attr_set) {
        cudaFuncSetAttribute(k_attn_mma, cudaFuncAttributeMaxDynamicSharedMemorySize,
                             KA_SMEM_FLOATS * sizeof(float));
        cudaFuncSetAttribute(k_fused_mma, cudaFuncAttributeMaxDynamicSharedMemorySize,
                             FM_SMEM_FLOATS * sizeof(float));
        attr_set = true;
    }

    k_prep<<<472, 256>>>(wd, bd);
    k_attn_mma<<<dim3(NS, 3), 256, KA_SMEM_FLOATS * sizeof(float)>>>(x, wa, ba, wb, bb);
    k_softmax<<<NS, 32>>>(A, W);
    k_fused_mma<<<dim3(Nn, 60), 256, FM_SMEM_FLOATS * sizeof(float)>>>(x, wd);
    k_final<<<30000, 256>>>(x, gamma, beta, out);
}